// round 5
// baseline (speedup 1.0000x reference)
#include <cuda_runtime.h>
#include <cstdint>

#define NN 1024
#define DD 256
#define HH 32
#define OUTS 64
#define NBINS 65

#define TI 16
#define TJ 16
#define NTILES 4096          // 64 x 64 tiles of 16x16 pairs
#define SPITCH 260           // sP pitch: 256 rows + 4 pad (16B multiple)

// scratch for projections (device globals: no allocation allowed)
__device__ float g_left[NN * HH];
__device__ float g_right[NN * HH];

// ---------------------------------------------------------------------------
__device__ __forceinline__ void fma2(unsigned long long& d,
                                     unsigned long long a,
                                     unsigned long long b) {
    asm("fma.rn.f32x2 %0, %1, %2, %0;" : "+l"(d) : "l"(a), "l"(b));
}
__device__ __forceinline__ float2 up2(unsigned long long a) {
    float2 f;
    asm("mov.b64 {%0, %1}, %2;" : "=f"(f.x), "=f"(f.y) : "l"(a));
    return f;
}

// JAX approximate (tanh) GELU; tanh(u) = 1 - 2/(1+exp(2u))
__device__ __forceinline__ float gelu_tanh(float x) {
    float u = 0.7978845608028654f * (x + 0.044715f * x * x * x);
    float e = __expf(2.0f * u);
    float t = 1.0f - __fdividef(2.0f, 1.0f + e);
    return 0.5f * x * (1.0f + t);
}

// ---------------------------------------------------------------------------
// Projection: left = local @ W_left, right = local @ W_right [1024,256]@[256,32]
// ---------------------------------------------------------------------------
__global__ void proj_kernel(const float* __restrict__ local,
                            const float* __restrict__ Wl,
                            const float* __restrict__ Wr) {
    int idx  = blockIdx.x * blockDim.x + threadIdx.x;
    int h    = idx & 31;
    int n    = (idx >> 5) & (NN - 1);
    int side = idx >> 15;
    const float* W = side ? Wr : Wl;
    float*       g = side ? g_right : g_left;

    const float4* row4 = reinterpret_cast<const float4*>(local + (size_t)n * DD);
    float acc = 0.f;
#pragma unroll
    for (int d4 = 0; d4 < DD / 4; ++d4) {
        float4 r = row4[d4];
        int d = d4 * 4;
        acc += r.x * W[(d + 0) * HH + h];
        acc += r.y * W[(d + 1) * HH + h];
        acc += r.z * W[(d + 2) * HH + h];
        acc += r.w * W[(d + 3) * HH + h];
    }
    g[n * HH + h] = acc;
}

// ---------------------------------------------------------------------------
// Shared layout (float offsets). Weights duplicated: [.., w, w, ..] so packed
// f32x2 B operands load directly with zero MOVs.
// ---------------------------------------------------------------------------
#define OFF_WHD   0                        // 32*64  = 2048
#define OFF_WOD   (OFF_WHD + 2048)         // 32*128 = 4096
#define OFF_REL   (OFF_WOD + 4096)         // 65*36  = 2340
#define OFF_SC    (OFF_REL + 2340)         // 32
#define OFF_OF    (OFF_SC + 32)            // 32
#define OFF_BATCH (OFF_OF + 32)            // 1024 (int)
#define OFF_CHAIN (OFF_BATCH + 1024)       // 1024
#define OFF_RESI  (OFF_CHAIN + 1024)       // 1024
#define OFF_MASK  (OFF_RESI + 1024)        // 1024
#define OFF_PM    (OFF_MASK + 1024)        // 256 (int)
#define OFF_P     (OFF_PM + 256)           // 32*SPITCH = 8320 (pair, then hidden)
#define SMEM_FLOATS (OFF_P + 32 * SPITCH)  // 21220 floats
#define SMEM_BYTES  (SMEM_FLOATS * 4)      // ~84.9 KB -> 2 CTAs/SM

// ---------------------------------------------------------------------------
// Persistent fused pair kernel
// ---------------------------------------------------------------------------
__global__ __launch_bounds__(256, 2)
void pair_kernel(const int* __restrict__ resi,
                 const int* __restrict__ chain,
                 const int* __restrict__ batch,
                 const int* __restrict__ mask,
                 const float* __restrict__ W_relpos,
                 const float* __restrict__ ln_scale,
                 const float* __restrict__ ln_offset,
                 const float* __restrict__ W_hidden,
                 const float* __restrict__ W_out,
                 float* __restrict__ out) {
    extern __shared__ float sm[];
    float* sWhD = sm + OFF_WHD;
    float* sWoD = sm + OFF_WOD;
    float* sRel = sm + OFF_REL;
    float* sSc  = sm + OFF_SC;
    float* sOf  = sm + OFF_OF;
    int*   sB   = (int*)(sm + OFF_BATCH);
    int*   sC   = (int*)(sm + OFF_CHAIN);
    int*   sRs  = (int*)(sm + OFF_RESI);
    int*   sM   = (int*)(sm + OFF_MASK);
    int*   sPM  = (int*)(sm + OFF_PM);
    float* sP   = sm + OFF_P;

    const int t  = threadIdx.x;
    const int rg = t >> 3;     // 32 rowgroups x 8 rows (GEMM1+GEMM2)
    const int cg = t & 7;      // 8 colgroups

    // ---- one-time staging ----
    for (int idx = t; idx < HH * 2 * HH; idx += 256) {        // WhD duplicated
        int k = idx >> 6, c = (idx & 63) >> 1;
        sWhD[idx] = W_hidden[k * HH + c];
    }
    for (int idx = t; idx < HH * 2 * OUTS; idx += 256) {      // WoD duplicated
        int k = idx >> 7, c = (idx & 127) >> 1;
        sWoD[idx] = W_out[k * OUTS + c];
    }
    for (int idx = t; idx < NBINS * HH; idx += 256)
        sRel[(idx >> 5) * 36 + (idx & 31)] = W_relpos[idx];
    for (int idx = t; idx < NN; idx += 256) {
        sB[idx]  = batch[idx];
        sC[idx]  = chain[idx];
        sRs[idx] = resi[idx];
        sM[idx]  = mask[idx];
    }
    if (t < HH) { sSc[t] = ln_scale[t]; sOf[t] = ln_offset[t]; }
    __syncthreads();

    const float4 z4 = make_float4(0.f, 0.f, 0.f, 0.f);

    // ---- persistent tile loop ----
    for (int tile = blockIdx.x; tile < NTILES; tile += gridDim.x) {
        const int i0 = (tile >> 6) << 4, j0 = (tile & 63) << 4;
        const int i = i0 + (t >> 4), j = j0 + (t & 15);

        const bool pm = (sB[i] == sB[j]) && (sM[i] != 0) && (sM[j] != 0);
        // barrier: also orders previous iteration's sP/sPM reads before reuse
        const int any = __syncthreads_or((int)pm);
        if (!any) {
#pragma unroll
            for (int r8 = 0; r8 < 8; ++r8) {
                const int r = rg * 8 + r8;
                float* ob = out + ((size_t)((i0 + (r >> 4)) * NN + j0 + (r & 15))) * OUTS
                                + cg * 8;
                __stcs(reinterpret_cast<float4*>(ob), z4);
                __stcs(reinterpret_cast<float4*>(ob) + 1, z4);
            }
            continue;
        }
        sPM[t] = pm;

        // ---- Phase A: pair build + layernorm -> sP K-major ----
        if (pm) {
            const bool same_chain = (sC[i] == sC[j]);
            int diff = sRs[i] - sRs[j];
            diff = min(max(diff, -32), 32) + 32;

            const float4* lp = reinterpret_cast<const float4*>(g_left + i * HH);
            const float4* rp = reinterpret_cast<const float4*>(g_right + j * HH);
            const float4* ep = reinterpret_cast<const float4*>(&sRel[diff * 36]);

            float p[HH];
            float mu = 0.f;
#pragma unroll
            for (int h4 = 0; h4 < 8; ++h4) {
                float4 l = lp[h4], r = rp[h4], e = ep[h4];
                float4 v;
                v.x = l.x + r.x; v.y = l.y + r.y; v.z = l.z + r.z; v.w = l.w + r.w;
                if (same_chain) { v.x += e.x; v.y += e.y; v.z += e.z; v.w += e.w; }
                p[h4 * 4 + 0] = v.x; p[h4 * 4 + 1] = v.y;
                p[h4 * 4 + 2] = v.z; p[h4 * 4 + 3] = v.w;
                mu += v.x + v.y + v.z + v.w;
            }
            mu *= (1.f / HH);
            float var = 0.f;
#pragma unroll
            for (int h = 0; h < HH; ++h) { float d = p[h] - mu; var += d * d; }
            var *= (1.f / HH);
            const float rstd = rsqrtf(var + 1e-5f);
#pragma unroll
            for (int h = 0; h < HH; ++h)
                sP[h * SPITCH + t] = (p[h] - mu) * rstd * sSc[h] + sOf[h];
        } else {
#pragma unroll
            for (int h = 0; h < HH; ++h) sP[h * SPITCH + t] = 0.f;
        }
        __syncthreads();

        // ---- GEMM1: hid[256x32] = gelu(P @ Wh); 8 rows x 4 cols / thread ----
        float hv[4][8];   // [col][row] gelu'd
        {
            unsigned long long acc1[4][4];   // [rowpair][col]
#pragma unroll
            for (int a = 0; a < 4; ++a)
#pragma unroll
                for (int b = 0; b < 4; ++b) acc1[a][b] = 0ull;

#pragma unroll
            for (int k = 0; k < HH; ++k) {
                const ulonglong2 A0 =
                    *reinterpret_cast<const ulonglong2*>(&sP[k * SPITCH + rg * 8]);
                const ulonglong2 A1 =
                    *reinterpret_cast<const ulonglong2*>(&sP[k * SPITCH + rg * 8 + 4]);
                const ulonglong2 B0 =
                    *reinterpret_cast<const ulonglong2*>(&sWhD[k * 64 + cg * 8]);
                const ulonglong2 B1 =
                    *reinterpret_cast<const ulonglong2*>(&sWhD[k * 64 + cg * 8 + 4]);
                const unsigned long long ar[4] = {A0.x, A0.y, A1.x, A1.y};
                const unsigned long long bc[4] = {B0.x, B0.y, B1.x, B1.y};
#pragma unroll
                for (int rp = 0; rp < 4; ++rp)
#pragma unroll
                    for (int c = 0; c < 4; ++c) fma2(acc1[rp][c], ar[rp], bc[c]);
            }
#pragma unroll
            for (int rp = 0; rp < 4; ++rp)
#pragma unroll
                for (int c = 0; c < 4; ++c) {
                    float2 v = up2(acc1[rp][c]);
                    hv[c][2 * rp]     = gelu_tanh(v.x);
                    hv[c][2 * rp + 1] = gelu_tanh(v.y);
                }
        }
        __syncthreads();   // all reads of sP (pair) done

        // write hidden K-major into aliased sP
#pragma unroll
        for (int c = 0; c < 4; ++c) {
            const int col = cg * 4 + c;
            *reinterpret_cast<float4*>(&sP[col * SPITCH + rg * 8]) =
                make_float4(hv[c][0], hv[c][1], hv[c][2], hv[c][3]);
            *reinterpret_cast<float4*>(&sP[col * SPITCH + rg * 8 + 4]) =
                make_float4(hv[c][4], hv[c][5], hv[c][6], hv[c][7]);
        }
        __syncthreads();

        // ---- GEMM2: out[256x64] = hid @ Wo; 8 rows x 8 cols / thread ----
        {
            unsigned long long acc[4][8];    // [rowpair][col]
#pragma unroll
            for (int a = 0; a < 4; ++a)
#pragma unroll
                for (int b = 0; b < 8; ++b) acc[a][b] = 0ull;

#pragma unroll
            for (int k = 0; k < HH; ++k) {
                const ulonglong2 A0 =
                    *reinterpret_cast<const ulonglong2*>(&sP[k * SPITCH + rg * 8]);
                const ulonglong2 A1 =
                    *reinterpret_cast<const ulonglong2*>(&sP[k * SPITCH + rg * 8 + 4]);
                const ulonglong2 B0 =
                    *reinterpret_cast<const ulonglong2*>(&sWoD[k * 128 + cg * 16]);
                const ulonglong2 B1 =
                    *reinterpret_cast<const ulonglong2*>(&sWoD[k * 128 + cg * 16 + 4]);
                const ulonglong2 B2 =
                    *reinterpret_cast<const ulonglong2*>(&sWoD[k * 128 + cg * 16 + 8]);
                const ulonglong2 B3 =
                    *reinterpret_cast<const ulonglong2*>(&sWoD[k * 128 + cg * 16 + 12]);
                const unsigned long long ar[4] = {A0.x, A0.y, A1.x, A1.y};
                const unsigned long long bc[8] = {B0.x, B0.y, B1.x, B1.y,
                                                  B2.x, B2.y, B3.x, B3.y};
#pragma unroll
                for (int rp = 0; rp < 4; ++rp)
#pragma unroll
                    for (int c = 0; c < 8; ++c) fma2(acc[rp][c], ar[rp], bc[c]);
            }

            // stores: rows rg*8+2rp(+parity); cols cg*8..+7 (256B/8 lanes, coalesced)
#pragma unroll
            for (int rp = 0; rp < 4; ++rp) {
                const int r0 = rg * 8 + 2 * rp, r1 = r0 + 1;
                float* ob0 = out + ((size_t)((i0 + (r0 >> 4)) * NN + j0 + (r0 & 15))) * OUTS
                                 + cg * 8;
                float* ob1 = out + ((size_t)((i0 + (r1 >> 4)) * NN + j0 + (r1 & 15))) * OUTS
                                 + cg * 8;
                float2 v0 = up2(acc[rp][0]), v1 = up2(acc[rp][1]);
                float2 v2 = up2(acc[rp][2]), v3 = up2(acc[rp][3]);
                float2 v4 = up2(acc[rp][4]), v5 = up2(acc[rp][5]);
                float2 v6 = up2(acc[rp][6]), v7 = up2(acc[rp][7]);
                if (sPM[r0]) {
                    __stcs(reinterpret_cast<float4*>(ob0),
                           make_float4(v0.x, v1.x, v2.x, v3.x));
                    __stcs(reinterpret_cast<float4*>(ob0) + 1,
                           make_float4(v4.x, v5.x, v6.x, v7.x));
                } else {
                    __stcs(reinterpret_cast<float4*>(ob0), z4);
                    __stcs(reinterpret_cast<float4*>(ob0) + 1, z4);
                }
                if (sPM[r1]) {
                    __stcs(reinterpret_cast<float4*>(ob1),
                           make_float4(v0.y, v1.y, v2.y, v3.y));
                    __stcs(reinterpret_cast<float4*>(ob1) + 1,
                           make_float4(v4.y, v5.y, v6.y, v7.y));
                } else {
                    __stcs(reinterpret_cast<float4*>(ob1), z4);
                    __stcs(reinterpret_cast<float4*>(ob1) + 1, z4);
                }
            }
        }
    }
}

// ---------------------------------------------------------------------------
extern "C" void kernel_launch(void* const* d_in, const int* in_sizes, int n_in,
                              void* d_out, int out_size) {
    const float* local = (const float*)d_in[0];
    const int*   resi  = (const int*)d_in[1];
    const int*   chain = (const int*)d_in[2];
    const int*   batch = (const int*)d_in[3];
    const int*   mask  = (const int*)d_in[4];
    const float* Wl    = (const float*)d_in[5];
    const float* Wr    = (const float*)d_in[6];
    const float* Wrel  = (const float*)d_in[7];
    const float* lns   = (const float*)d_in[8];
    const float* lno   = (const float*)d_in[9];
    const float* Wh    = (const float*)d_in[10];
    const float* Wo    = (const float*)d_in[11];
    float*       out   = (float*)d_out;

    static int nCTA = 0;
    if (nCTA == 0) {
        cudaFuncSetAttribute(pair_kernel,
                             cudaFuncAttributeMaxDynamicSharedMemorySize,
                             SMEM_BYTES);
        int dev = 0, sms = 148;
        cudaGetDevice(&dev);
        cudaDeviceGetAttribute(&sms, cudaDevAttrMultiProcessorCount, dev);
        nCTA = 2 * sms;
    }

    proj_kernel<<<256, 256>>>(local, Wl, Wr);
    pair_kernel<<<nCTA, 256, SMEM_BYTES>>>(resi, chain, batch, mask, Wrel,
                                           lns, lno, Wh, Wo, out);
}

// round 7
// speedup vs baseline: 1.6726x; 1.6726x over previous
#include <cuda_runtime.h>
#include <cstdint>

#define NN 1024
#define DD 256
#define HH 32
#define OUTS 64
#define NBINS 65
#define SPITCH 260   // sP pitch: 256 rows + 4 pad (16B multiple)

// scratch for projections (device globals: no allocation allowed)
__device__ float g_left[NN * HH];
__device__ float g_right[NN * HH];

// ---------------------------------------------------------------------------
__device__ __forceinline__ void fma2(unsigned long long& d,
                                     unsigned long long a,
                                     unsigned long long b) {
    asm("fma.rn.f32x2 %0, %1, %2, %0;" : "+l"(d) : "l"(a), "l"(b));
}
__device__ __forceinline__ float2 up2(unsigned long long a) {
    float2 f;
    asm("mov.b64 {%0, %1}, %2;" : "=f"(f.x), "=f"(f.y) : "l"(a));
    return f;
}

// JAX approximate (tanh) GELU; tanh(u) = 1 - 2/(1+exp(2u))
__device__ __forceinline__ float gelu_tanh(float x) {
    float u = 0.7978845608028654f * (x + 0.044715f * x * x * x);
    float e = __expf(2.0f * u);
    float t = 1.0f - __fdividef(2.0f, 1.0f + e);
    return 0.5f * x * (1.0f + t);
}

// ---------------------------------------------------------------------------
// Projection: left = local @ W_left, right = local @ W_right [1024,256]@[256,32]
// ---------------------------------------------------------------------------
__global__ void proj_kernel(const float* __restrict__ local,
                            const float* __restrict__ Wl,
                            const float* __restrict__ Wr) {
    int idx  = blockIdx.x * blockDim.x + threadIdx.x;
    int h    = idx & 31;
    int n    = (idx >> 5) & (NN - 1);
    int side = idx >> 15;
    const float* W = side ? Wr : Wl;
    float*       g = side ? g_right : g_left;

    const float4* row4 = reinterpret_cast<const float4*>(local + (size_t)n * DD);
    float acc = 0.f;
#pragma unroll
    for (int d4 = 0; d4 < DD / 4; ++d4) {
        float4 r = row4[d4];
        int d = d4 * 4;
        acc += r.x * W[(d + 0) * HH + h];
        acc += r.y * W[(d + 1) * HH + h];
        acc += r.z * W[(d + 2) * HH + h];
        acc += r.w * W[(d + 3) * HH + h];
    }
    g[n * HH + h] = acc;
}

// ---------------------------------------------------------------------------
// Shared layout (float offsets). Weights stored DUPLICATED ([w,w] pairs) so
// packed f32x2 B operands load directly from LDS.128 with zero MOVs.
// ---------------------------------------------------------------------------
#define OFF_WHD  0                        // 32*64  = 2048
#define OFF_WOD  (OFF_WHD + 2048)         // 32*128 = 4096
#define OFF_REL  (OFF_WOD + 4096)         // 65*36  = 2340
#define OFF_L    (OFF_REL + 2340)         // 16*32  = 512
#define OFF_R    (OFF_L + 512)            // 512
#define OFF_SC   (OFF_R + 512)            // 32
#define OFF_OF   (OFF_SC + 32)            // 32
#define OFF_PM   (OFF_OF + 32)            // 256 (int)
#define OFF_P    (OFF_PM + 256)           // 32*SPITCH = 8320 (pair, then hidden)
#define SMEM_FLOATS (OFF_P + 32 * SPITCH) // 18144 floats
#define SMEM_BYTES  (SMEM_FLOATS * 4)     // ~72.6 KB -> 2 CTAs/SM (regs bind anyway)

// ---------------------------------------------------------------------------
// Fused pair kernel: 16x16-pair tiles, 256 threads, two zero-MOV f32x2 GEMMs
// ---------------------------------------------------------------------------
__global__ __launch_bounds__(256, 2)
void pair_kernel(const int* __restrict__ resi,
                 const int* __restrict__ chain,
                 const int* __restrict__ batch,
                 const int* __restrict__ mask,
                 const float* __restrict__ W_relpos,
                 const float* __restrict__ ln_scale,
                 const float* __restrict__ ln_offset,
                 const float* __restrict__ W_hidden,
                 const float* __restrict__ W_out,
                 float* __restrict__ out) {
    extern __shared__ float sm[];
    float* sWhD = sm + OFF_WHD;
    float* sWoD = sm + OFF_WOD;
    float* sRel = sm + OFF_REL;
    float* sL   = sm + OFF_L;
    float* sR   = sm + OFF_R;
    float* sSc  = sm + OFF_SC;
    float* sOf  = sm + OFF_OF;
    int*   sPM  = (int*)(sm + OFF_PM);
    float* sP   = sm + OFF_P;

    const int t  = threadIdx.x;
    const int i0 = blockIdx.y * 16, j0 = blockIdx.x * 16;
    const int ty = t >> 4, tx = t & 15;
    const int i = i0 + ty, j = j0 + tx;
    const int rg = t >> 3, cg = t & 7;   // 32 rowgroups x 8 colgroups

    // ---- per-pair mask; block-level early exit ----
    const bool pm = (batch[i] == batch[j]) && (mask[i] != 0) && (mask[j] != 0);
    sPM[t] = pm;
    const int any = __syncthreads_or((int)pm);

    const float4 z4 = make_float4(0.f, 0.f, 0.f, 0.f);
    if (!any) {
#pragma unroll
        for (int r8 = 0; r8 < 8; ++r8) {
            const int r = rg * 8 + r8;
            float* ob = out + ((size_t)((i0 + (r >> 4)) * NN + j0 + (r & 15))) * OUTS
                            + cg * 8;
            __stcs(reinterpret_cast<float4*>(ob), z4);
            __stcs(reinterpret_cast<float4*>(ob) + 1, z4);
        }
        return;
    }

    // ---- stage weights (duplicated), rel table, L/R tiles ----
    for (int idx = t; idx < HH * 2 * HH; idx += 256) {         // WhD
        int k = idx >> 6, c = (idx & 63) >> 1;
        sWhD[idx] = W_hidden[k * HH + c];
    }
    for (int idx = t; idx < HH * 2 * OUTS; idx += 256) {       // WoD
        int k = idx >> 7, c = (idx & 127) >> 1;
        sWoD[idx] = W_out[k * OUTS + c];
    }
    for (int idx = t; idx < NBINS * HH; idx += 256)
        sRel[(idx >> 5) * 36 + (idx & 31)] = W_relpos[idx];
    for (int idx = t; idx < 16 * HH; idx += 256) {
        sL[idx] = g_left[i0 * HH + idx];
        sR[idx] = g_right[j0 * HH + idx];
    }
    if (t < HH) { sSc[t] = ln_scale[t]; sOf[t] = ln_offset[t]; }
    __syncthreads();

    // ---- Phase A: pair build + layernorm -> sP K-major ----
    {
        const bool same_chain = (batch[i] == batch[j]) && (chain[i] == chain[j]);
        int diff = resi[i] - resi[j];
        diff = min(max(diff, -32), 32) + 32;

        const float4* lp = reinterpret_cast<const float4*>(sL + ty * HH);
        const float4* rp = reinterpret_cast<const float4*>(sR + tx * HH);
        const float4* ep = reinterpret_cast<const float4*>(&sRel[diff * 36]);

        float p[HH];
        float mu = 0.f;
#pragma unroll
        for (int h4 = 0; h4 < 8; ++h4) {
            float4 l = lp[h4], r = rp[h4], e = ep[h4];
            float4 v;
            v.x = l.x + r.x; v.y = l.y + r.y; v.z = l.z + r.z; v.w = l.w + r.w;
            if (same_chain) { v.x += e.x; v.y += e.y; v.z += e.z; v.w += e.w; }
            p[h4 * 4 + 0] = v.x; p[h4 * 4 + 1] = v.y;
            p[h4 * 4 + 2] = v.z; p[h4 * 4 + 3] = v.w;
            mu += v.x + v.y + v.z + v.w;
        }
        mu *= (1.f / HH);
        float var = 0.f;
#pragma unroll
        for (int h = 0; h < HH; ++h) { float d = p[h] - mu; var += d * d; }
        var *= (1.f / HH);
        const float rstd = rsqrtf(var + 1e-5f);
#pragma unroll
        for (int h = 0; h < HH; ++h)
            sP[h * SPITCH + t] = (p[h] - mu) * rstd * sSc[h] + sOf[h];
    }
    __syncthreads();

    // ---- GEMM1: hid[256x32] = gelu(P @ Wh); 8 rows x 4 cols / thread ----
    float hv[4][8];   // [col][row]
    {
        unsigned long long acc1[4][4];   // [rowpair][col]
#pragma unroll
        for (int a = 0; a < 4; ++a)
#pragma unroll
            for (int b = 0; b < 4; ++b) acc1[a][b] = 0ull;

#pragma unroll
        for (int k = 0; k < HH; ++k) {
            const ulonglong2 A0 =
                *reinterpret_cast<const ulonglong2*>(&sP[k * SPITCH + rg * 8]);
            const ulonglong2 A1 =
                *reinterpret_cast<const ulonglong2*>(&sP[k * SPITCH + rg * 8 + 4]);
            const ulonglong2 B0 =
                *reinterpret_cast<const ulonglong2*>(&sWhD[k * 64 + cg * 8]);
            const ulonglong2 B1 =
                *reinterpret_cast<const ulonglong2*>(&sWhD[k * 64 + cg * 8 + 4]);
            const unsigned long long ar[4] = {A0.x, A0.y, A1.x, A1.y};
            const unsigned long long bc[4] = {B0.x, B0.y, B1.x, B1.y};
#pragma unroll
            for (int rp = 0; rp < 4; ++rp)
#pragma unroll
                for (int c = 0; c < 4; ++c) fma2(acc1[rp][c], ar[rp], bc[c]);
        }
#pragma unroll
        for (int rp = 0; rp < 4; ++rp)
#pragma unroll
            for (int c = 0; c < 4; ++c) {
                float2 v = up2(acc1[rp][c]);
                hv[c][2 * rp]     = gelu_tanh(v.x);
                hv[c][2 * rp + 1] = gelu_tanh(v.y);
            }
    }
    __syncthreads();   // all reads of sP (pair) done

    // write hidden K-major into aliased sP
#pragma unroll
    for (int c = 0; c < 4; ++c) {
        const int col = cg * 4 + c;
        *reinterpret_cast<float4*>(&sP[col * SPITCH + rg * 8]) =
            make_float4(hv[c][0], hv[c][1], hv[c][2], hv[c][3]);
        *reinterpret_cast<float4*>(&sP[col * SPITCH + rg * 8 + 4]) =
            make_float4(hv[c][4], hv[c][5], hv[c][6], hv[c][7]);
    }
    __syncthreads();

    // ---- GEMM2: out[256x64] = hid @ Wo; 8 rows x 8 cols / thread ----
    {
        unsigned long long acc[4][8];    // [rowpair][col]
#pragma unroll
        for (int a = 0; a < 4; ++a)
#pragma unroll
            for (int b = 0; b < 8; ++b) acc[a][b] = 0ull;

#pragma unroll
        for (int k = 0; k < HH; ++k) {
            const ulonglong2 A0 =
                *reinterpret_cast<const ulonglong2*>(&sP[k * SPITCH + rg * 8]);
            const ulonglong2 A1 =
                *reinterpret_cast<const ulonglong2*>(&sP[k * SPITCH + rg * 8 + 4]);
            const ulonglong2 B0 =
                *reinterpret_cast<const ulonglong2*>(&sWoD[k * 128 + cg * 16]);
            const ulonglong2 B1 =
                *reinterpret_cast<const ulonglong2*>(&sWoD[k * 128 + cg * 16 + 4]);
            const ulonglong2 B2 =
                *reinterpret_cast<const ulonglong2*>(&sWoD[k * 128 + cg * 16 + 8]);
            const ulonglong2 B3 =
                *reinterpret_cast<const ulonglong2*>(&sWoD[k * 128 + cg * 16 + 12]);
            const unsigned long long ar[4] = {A0.x, A0.y, A1.x, A1.y};
            const unsigned long long bc[8] = {B0.x, B0.y, B1.x, B1.y,
                                              B2.x, B2.y, B3.x, B3.y};
#pragma unroll
            for (int rp = 0; rp < 4; ++rp)
#pragma unroll
                for (int c = 0; c < 8; ++c) fma2(acc[rp][c], ar[rp], bc[c]);
        }

        // stores: rows rg*8+2rp(+parity); cols cg*8..+7 -> contiguous 256B/8 lanes
#pragma unroll
        for (int rp = 0; rp < 4; ++rp) {
            const int r0 = rg * 8 + 2 * rp, r1 = r0 + 1;
            float* ob0 = out + ((size_t)((i0 + (r0 >> 4)) * NN + j0 + (r0 & 15))) * OUTS
                             + cg * 8;
            float* ob1 = out + ((size_t)((i0 + (r1 >> 4)) * NN + j0 + (r1 & 15))) * OUTS
                             + cg * 8;
            float2 v0 = up2(acc[rp][0]), v1 = up2(acc[rp][1]);
            float2 v2 = up2(acc[rp][2]), v3 = up2(acc[rp][3]);
            float2 v4 = up2(acc[rp][4]), v5 = up2(acc[rp][5]);
            float2 v6 = up2(acc[rp][6]), v7 = up2(acc[rp][7]);
            if (sPM[r0]) {
                __stcs(reinterpret_cast<float4*>(ob0),
                       make_float4(v0.x, v1.x, v2.x, v3.x));
                __stcs(reinterpret_cast<float4*>(ob0) + 1,
                       make_float4(v4.x, v5.x, v6.x, v7.x));
            } else {
                __stcs(reinterpret_cast<float4*>(ob0), z4);
                __stcs(reinterpret_cast<float4*>(ob0) + 1, z4);
            }
            if (sPM[r1]) {
                __stcs(reinterpret_cast<float4*>(ob1),
                       make_float4(v0.y, v1.y, v2.y, v3.y));
                __stcs(reinterpret_cast<float4*>(ob1) + 1,
                       make_float4(v4.y, v5.y, v6.y, v7.y));
            } else {
                __stcs(reinterpret_cast<float4*>(ob1), z4);
                __stcs(reinterpret_cast<float4*>(ob1) + 1, z4);
            }
        }
    }
}

// ---------------------------------------------------------------------------
extern "C" void kernel_launch(void* const* d_in, const int* in_sizes, int n_in,
                              void* d_out, int out_size) {
    const float* local = (const float*)d_in[0];
    const int*   resi  = (const int*)d_in[1];
    const int*   chain = (const int*)d_in[2];
    const int*   batch = (const int*)d_in[3];
    const int*   mask  = (const int*)d_in[4];
    const float* Wl    = (const float*)d_in[5];
    const float* Wr    = (const float*)d_in[6];
    const float* Wrel  = (const float*)d_in[7];
    const float* lns   = (const float*)d_in[8];
    const float* lno   = (const float*)d_in[9];
    const float* Wh    = (const float*)d_in[10];
    const float* Wo    = (const float*)d_in[11];
    float*       out   = (float*)d_out;

    static bool attr_set = false;
    if (!attr_set) {
        cudaFuncSetAttribute(pair_kernel,
                             cudaFuncAttributeMaxDynamicSharedMemorySize,
                             SMEM_BYTES);
        attr_set = true;
    }

    proj_kernel<<<256, 256>>>(local, Wl, Wr);

    dim3 grid(NN / 16, NN / 16);
    pair_kernel<<<grid, 256, SMEM_BYTES>>>(resi, chain, batch, mask, Wrel,
                                           lns, lno, Wh, Wo, out);
}

// round 8
// speedup vs baseline: 1.6734x; 1.0005x over previous
#include <cuda_runtime.h>
#include <cstdint>

#define NN 1024
#define DD 256
#define HH 32
#define OUTS 64
#define NBINS 65
#define SPITCH 260   // sP pitch: 256 rows + 4 pad (16B multiple)

// scratch for projections (device globals: no allocation allowed)
__device__ float g_left[NN * HH];
__device__ float g_right[NN * HH];

// ---------------------------------------------------------------------------
__device__ __forceinline__ void fma2(unsigned long long& d,
                                     unsigned long long a,
                                     unsigned long long b) {
    asm("fma.rn.f32x2 %0, %1, %2, %0;" : "+l"(d) : "l"(a), "l"(b));
}
__device__ __forceinline__ float2 up2(unsigned long long a) {
    float2 f;
    asm("mov.b64 {%0, %1}, %2;" : "=f"(f.x), "=f"(f.y) : "l"(a));
    return f;
}

// JAX approximate (tanh) GELU; tanh(u) = 1 - 2/(1+exp(2u))
__device__ __forceinline__ float gelu_tanh(float x) {
    float u = 0.7978845608028654f * (x + 0.044715f * x * x * x);
    float e = __expf(2.0f * u);
    float t = 1.0f - __fdividef(2.0f, 1.0f + e);
    return 0.5f * x * (1.0f + t);
}

// ---------------------------------------------------------------------------
// Projection: left = local @ W_left, right = local @ W_right [1024,256]@[256,32]
// ---------------------------------------------------------------------------
__global__ void proj_kernel(const float* __restrict__ local,
                            const float* __restrict__ Wl,
                            const float* __restrict__ Wr) {
    int idx  = blockIdx.x * blockDim.x + threadIdx.x;
    int h    = idx & 31;
    int n    = (idx >> 5) & (NN - 1);
    int side = idx >> 15;
    const float* W = side ? Wr : Wl;
    float*       g = side ? g_right : g_left;

    const float4* row4 = reinterpret_cast<const float4*>(local + (size_t)n * DD);
    float acc = 0.f;
#pragma unroll
    for (int d4 = 0; d4 < DD / 4; ++d4) {
        float4 r = row4[d4];
        int d = d4 * 4;
        acc += r.x * W[(d + 0) * HH + h];
        acc += r.y * W[(d + 1) * HH + h];
        acc += r.z * W[(d + 2) * HH + h];
        acc += r.w * W[(d + 3) * HH + h];
    }
    g[n * HH + h] = acc;
}

// ---------------------------------------------------------------------------
// Shared layout (float offsets). Weights stored DUPLICATED ([w,w] pairs) so
// packed f32x2 B operands load directly from LDS.128 with zero MOVs.
// ---------------------------------------------------------------------------
#define OFF_WHD  0                        // 32*64  = 2048
#define OFF_WOD  (OFF_WHD + 2048)         // 32*128 = 4096
#define OFF_REL  (OFF_WOD + 4096)         // 65*36  = 2340
#define OFF_L    (OFF_REL + 2340)         // 16*32  = 512
#define OFF_R    (OFF_L + 512)            // 512
#define OFF_SC   (OFF_R + 512)            // 32
#define OFF_OF   (OFF_SC + 32)            // 32
#define OFF_PM   (OFF_OF + 32)            // 256 (int)
#define OFF_P    (OFF_PM + 256)           // 32*SPITCH = 8320 (pair, then hidden)
#define SMEM_FLOATS (OFF_P + 32 * SPITCH) // 18144 floats
#define SMEM_BYTES  (SMEM_FLOATS * 4)     // ~72.6 KB -> 2 CTAs/SM (regs bind anyway)

// ---------------------------------------------------------------------------
// Fused pair kernel: 16x16-pair tiles, 256 threads, two zero-MOV f32x2 GEMMs
// ---------------------------------------------------------------------------
__global__ __launch_bounds__(256, 2)
void pair_kernel(const int* __restrict__ resi,
                 const int* __restrict__ chain,
                 const int* __restrict__ batch,
                 const int* __restrict__ mask,
                 const float* __restrict__ W_relpos,
                 const float* __restrict__ ln_scale,
                 const float* __restrict__ ln_offset,
                 const float* __restrict__ W_hidden,
                 const float* __restrict__ W_out,
                 float* __restrict__ out) {
    extern __shared__ float sm[];
    float* sWhD = sm + OFF_WHD;
    float* sWoD = sm + OFF_WOD;
    float* sRel = sm + OFF_REL;
    float* sL   = sm + OFF_L;
    float* sR   = sm + OFF_R;
    float* sSc  = sm + OFF_SC;
    float* sOf  = sm + OFF_OF;
    int*   sPM  = (int*)(sm + OFF_PM);
    float* sP   = sm + OFF_P;

    const int t  = threadIdx.x;
    const int i0 = blockIdx.y * 16, j0 = blockIdx.x * 16;
    const int ty = t >> 4, tx = t & 15;
    const int i = i0 + ty, j = j0 + tx;
    const int rg = t >> 3, cg = t & 7;   // 32 rowgroups x 8 colgroups

    // ---- per-pair mask; block-level early exit ----
    const bool pm = (batch[i] == batch[j]) && (mask[i] != 0) && (mask[j] != 0);
    sPM[t] = pm;
    const int any = __syncthreads_or((int)pm);

    const float4 z4 = make_float4(0.f, 0.f, 0.f, 0.f);
    if (!any) {
#pragma unroll
        for (int r8 = 0; r8 < 8; ++r8) {
            const int r = rg * 8 + r8;
            float* ob = out + ((size_t)((i0 + (r >> 4)) * NN + j0 + (r & 15))) * OUTS
                            + cg * 8;
            __stcs(reinterpret_cast<float4*>(ob), z4);
            __stcs(reinterpret_cast<float4*>(ob) + 1, z4);
        }
        return;
    }

    // ---- stage weights (duplicated), rel table, L/R tiles ----
    for (int idx = t; idx < HH * 2 * HH; idx += 256) {         // WhD
        int k = idx >> 6, c = (idx & 63) >> 1;
        sWhD[idx] = W_hidden[k * HH + c];
    }
    for (int idx = t; idx < HH * 2 * OUTS; idx += 256) {       // WoD
        int k = idx >> 7, c = (idx & 127) >> 1;
        sWoD[idx] = W_out[k * OUTS + c];
    }
    for (int idx = t; idx < NBINS * HH; idx += 256)
        sRel[(idx >> 5) * 36 + (idx & 31)] = W_relpos[idx];
    for (int idx = t; idx < 16 * HH; idx += 256) {
        sL[idx] = g_left[i0 * HH + idx];
        sR[idx] = g_right[j0 * HH + idx];
    }
    if (t < HH) { sSc[t] = ln_scale[t]; sOf[t] = ln_offset[t]; }
    __syncthreads();

    // ---- Phase A: pair build + layernorm -> sP K-major ----
    {
        const bool same_chain = (batch[i] == batch[j]) && (chain[i] == chain[j]);
        int diff = resi[i] - resi[j];
        diff = min(max(diff, -32), 32) + 32;

        const float4* lp = reinterpret_cast<const float4*>(sL + ty * HH);
        const float4* rp = reinterpret_cast<const float4*>(sR + tx * HH);
        const float4* ep = reinterpret_cast<const float4*>(&sRel[diff * 36]);

        float p[HH];
        float mu = 0.f;
#pragma unroll
        for (int h4 = 0; h4 < 8; ++h4) {
            float4 l = lp[h4], r = rp[h4], e = ep[h4];
            float4 v;
            v.x = l.x + r.x; v.y = l.y + r.y; v.z = l.z + r.z; v.w = l.w + r.w;
            if (same_chain) { v.x += e.x; v.y += e.y; v.z += e.z; v.w += e.w; }
            p[h4 * 4 + 0] = v.x; p[h4 * 4 + 1] = v.y;
            p[h4 * 4 + 2] = v.z; p[h4 * 4 + 3] = v.w;
            mu += v.x + v.y + v.z + v.w;
        }
        mu *= (1.f / HH);
        float var = 0.f;
#pragma unroll
        for (int h = 0; h < HH; ++h) { float d = p[h] - mu; var += d * d; }
        var *= (1.f / HH);
        const float rstd = rsqrtf(var + 1e-5f);
#pragma unroll
        for (int h = 0; h < HH; ++h)
            sP[h * SPITCH + t] = (p[h] - mu) * rstd * sSc[h] + sOf[h];
    }
    __syncthreads();

    // ---- GEMM1: hid[256x32] = gelu(P @ Wh); 8 rows x 4 cols / thread ----
    float hv[4][8];   // [col][row]
    {
        unsigned long long acc1[4][4];   // [rowpair][col]
#pragma unroll
        for (int a = 0; a < 4; ++a)
#pragma unroll
            for (int b = 0; b < 4; ++b) acc1[a][b] = 0ull;

#pragma unroll
        for (int k = 0; k < HH; ++k) {
            const ulonglong2 A0 =
                *reinterpret_cast<const ulonglong2*>(&sP[k * SPITCH + rg * 8]);
            const ulonglong2 A1 =
                *reinterpret_cast<const ulonglong2*>(&sP[k * SPITCH + rg * 8 + 4]);
            const ulonglong2 B0 =
                *reinterpret_cast<const ulonglong2*>(&sWhD[k * 64 + cg * 8]);
            const ulonglong2 B1 =
                *reinterpret_cast<const ulonglong2*>(&sWhD[k * 64 + cg * 8 + 4]);
            const unsigned long long ar[4] = {A0.x, A0.y, A1.x, A1.y};
            const unsigned long long bc[4] = {B0.x, B0.y, B1.x, B1.y};
#pragma unroll
            for (int rp = 0; rp < 4; ++rp)
#pragma unroll
                for (int c = 0; c < 4; ++c) fma2(acc1[rp][c], ar[rp], bc[c]);
        }
#pragma unroll
        for (int rp = 0; rp < 4; ++rp)
#pragma unroll
            for (int c = 0; c < 4; ++c) {
                float2 v = up2(acc1[rp][c]);
                hv[c][2 * rp]     = gelu_tanh(v.x);
                hv[c][2 * rp + 1] = gelu_tanh(v.y);
            }
    }
    __syncthreads();   // all reads of sP (pair) done

    // write hidden K-major into aliased sP
#pragma unroll
    for (int c = 0; c < 4; ++c) {
        const int col = cg * 4 + c;
        *reinterpret_cast<float4*>(&sP[col * SPITCH + rg * 8]) =
            make_float4(hv[c][0], hv[c][1], hv[c][2], hv[c][3]);
        *reinterpret_cast<float4*>(&sP[col * SPITCH + rg * 8 + 4]) =
            make_float4(hv[c][4], hv[c][5], hv[c][6], hv[c][7]);
    }
    __syncthreads();

    // ---- GEMM2: out[256x64] = hid @ Wo; 8 rows x 8 cols / thread ----
    {
        unsigned long long acc[4][8];    // [rowpair][col]
#pragma unroll
        for (int a = 0; a < 4; ++a)
#pragma unroll
            for (int b = 0; b < 8; ++b) acc[a][b] = 0ull;

#pragma unroll
        for (int k = 0; k < HH; ++k) {
            const ulonglong2 A0 =
                *reinterpret_cast<const ulonglong2*>(&sP[k * SPITCH + rg * 8]);
            const ulonglong2 A1 =
                *reinterpret_cast<const ulonglong2*>(&sP[k * SPITCH + rg * 8 + 4]);
            const ulonglong2 B0 =
                *reinterpret_cast<const ulonglong2*>(&sWoD[k * 128 + cg * 16]);
            const ulonglong2 B1 =
                *reinterpret_cast<const ulonglong2*>(&sWoD[k * 128 + cg * 16 + 4]);
            const ulonglong2 B2 =
                *reinterpret_cast<const ulonglong2*>(&sWoD[k * 128 + cg * 16 + 8]);
            const ulonglong2 B3 =
                *reinterpret_cast<const ulonglong2*>(&sWoD[k * 128 + cg * 16 + 12]);
            const unsigned long long ar[4] = {A0.x, A0.y, A1.x, A1.y};
            const unsigned long long bc[8] = {B0.x, B0.y, B1.x, B1.y,
                                              B2.x, B2.y, B3.x, B3.y};
#pragma unroll
            for (int rp = 0; rp < 4; ++rp)
#pragma unroll
                for (int c = 0; c < 8; ++c) fma2(acc[rp][c], ar[rp], bc[c]);
        }

        // stores: rows rg*8+2rp(+parity); cols cg*8..+7 -> contiguous 256B/8 lanes
#pragma unroll
        for (int rp = 0; rp < 4; ++rp) {
            const int r0 = rg * 8 + 2 * rp, r1 = r0 + 1;
            float* ob0 = out + ((size_t)((i0 + (r0 >> 4)) * NN + j0 + (r0 & 15))) * OUTS
                             + cg * 8;
            float* ob1 = out + ((size_t)((i0 + (r1 >> 4)) * NN + j0 + (r1 & 15))) * OUTS
                             + cg * 8;
            float2 v0 = up2(acc[rp][0]), v1 = up2(acc[rp][1]);
            float2 v2 = up2(acc[rp][2]), v3 = up2(acc[rp][3]);
            float2 v4 = up2(acc[rp][4]), v5 = up2(acc[rp][5]);
            float2 v6 = up2(acc[rp][6]), v7 = up2(acc[rp][7]);
            if (sPM[r0]) {
                __stcs(reinterpret_cast<float4*>(ob0),
                       make_float4(v0.x, v1.x, v2.x, v3.x));
                __stcs(reinterpret_cast<float4*>(ob0) + 1,
                       make_float4(v4.x, v5.x, v6.x, v7.x));
            } else {
                __stcs(reinterpret_cast<float4*>(ob0), z4);
                __stcs(reinterpret_cast<float4*>(ob0) + 1, z4);
            }
            if (sPM[r1]) {
                __stcs(reinterpret_cast<float4*>(ob1),
                       make_float4(v0.y, v1.y, v2.y, v3.y));
                __stcs(reinterpret_cast<float4*>(ob1) + 1,
                       make_float4(v4.y, v5.y, v6.y, v7.y));
            } else {
                __stcs(reinterpret_cast<float4*>(ob1), z4);
                __stcs(reinterpret_cast<float4*>(ob1) + 1, z4);
            }
        }
    }
}

// ---------------------------------------------------------------------------
extern "C" void kernel_launch(void* const* d_in, const int* in_sizes, int n_in,
                              void* d_out, int out_size) {
    const float* local = (const float*)d_in[0];
    const int*   resi  = (const int*)d_in[1];
    const int*   chain = (const int*)d_in[2];
    const int*   batch = (const int*)d_in[3];
    const int*   mask  = (const int*)d_in[4];
    const float* Wl    = (const float*)d_in[5];
    const float* Wr    = (const float*)d_in[6];
    const float* Wrel  = (const float*)d_in[7];
    const float* lns   = (const float*)d_in[8];
    const float* lno   = (const float*)d_in[9];
    const float* Wh    = (const float*)d_in[10];
    const float* Wo    = (const float*)d_in[11];
    float*       out   = (float*)d_out;

    static bool attr_set = false;
    if (!attr_set) {
        cudaFuncSetAttribute(pair_kernel,
                             cudaFuncAttributeMaxDynamicSharedMemorySize,
                             SMEM_BYTES);
        attr_set = true;
    }

    proj_kernel<<<256, 256>>>(local, Wl, Wr);

    dim3 grid(NN / 16, NN / 16);
    pair_kernel<<<grid, 256, SMEM_BYTES>>>(resi, chain, batch, mask, Wrel,
                                           lns, lno, Wh, Wo, out);
}

// round 9
// speedup vs baseline: 3.7930x; 2.2667x over previous
#include <cuda_runtime.h>
#include <cuda_bf16.h>
#include <cstdint>

#define NN 1024
#define DD 256
#define HH 32
#define OUTS 64
#define NBINS 65
#define PITCHB 40     // bf16 pitch for fragment arrays
#define PW 20         // pitch in uint32 words (20 mod 32 -> conflict-free frags)

// scratch for projections (device globals: no allocation allowed)
__device__ float g_left[NN * HH];
__device__ float g_right[NN * HH];

// ---------------------------------------------------------------------------
// helpers
// ---------------------------------------------------------------------------
__device__ __forceinline__ uint32_t pack_bf16(float xlo, float xhi) {
    uint32_t r;   // cvt.rn.bf16x2.f32 d, a, b : d.hi=cvt(a), d.lo=cvt(b)
    asm("cvt.rn.bf16x2.f32 %0, %1, %2;" : "=r"(r) : "f"(xhi), "f"(xlo));
    return r;
}
// split x0,x1 into (hi, lo) bf16x2 pairs: x = hi + lo (+O(2^-17))
__device__ __forceinline__ void split_pack(float x0, float x1,
                                           uint32_t& hi, uint32_t& lo) {
    __nv_bfloat16 h0 = __float2bfloat16_rn(x0);
    __nv_bfloat16 h1 = __float2bfloat16_rn(x1);
    float r0 = x0 - __bfloat162float(h0);
    float r1 = x1 - __bfloat162float(h1);
    hi = ((uint32_t)__bfloat16_as_ushort(h1) << 16) | __bfloat16_as_ushort(h0);
    lo = pack_bf16(r0, r1);
}
__device__ __forceinline__ void mma16816(float* c, const uint32_t* a,
                                         uint32_t b0, uint32_t b1) {
    asm("mma.sync.aligned.m16n8k16.row.col.f32.bf16.bf16.f32 "
        "{%0,%1,%2,%3}, {%4,%5,%6,%7}, {%8,%9}, {%0,%1,%2,%3};"
        : "+f"(c[0]), "+f"(c[1]), "+f"(c[2]), "+f"(c[3])
        : "r"(a[0]), "r"(a[1]), "r"(a[2]), "r"(a[3]), "r"(b0), "r"(b1));
}
// JAX approximate (tanh) GELU
__device__ __forceinline__ float gelu_tanh(float x) {
    float u = 0.7978845608028654f * (x + 0.044715f * x * x * x);
    float e = __expf(2.0f * u);
    float t = 1.0f - __fdividef(2.0f, 1.0f + e);
    return 0.5f * x * (1.0f + t);
}

// ---------------------------------------------------------------------------
// Projection: left = local @ W_left, right = local @ W_right [1024,256]@[256,32]
// ---------------------------------------------------------------------------
__global__ void proj_kernel(const float* __restrict__ local,
                            const float* __restrict__ Wl,
                            const float* __restrict__ Wr) {
    int idx  = blockIdx.x * blockDim.x + threadIdx.x;
    int h    = idx & 31;
    int n    = (idx >> 5) & (NN - 1);
    int side = idx >> 15;
    const float* W = side ? Wr : Wl;
    float*       g = side ? g_right : g_left;

    const float4* row4 = reinterpret_cast<const float4*>(local + (size_t)n * DD);
    float acc = 0.f;
#pragma unroll
    for (int d4 = 0; d4 < DD / 4; ++d4) {
        float4 r = row4[d4];
        int d = d4 * 4;
        acc += r.x * W[(d + 0) * HH + h];
        acc += r.y * W[(d + 1) * HH + h];
        acc += r.z * W[(d + 2) * HH + h];
        acc += r.w * W[(d + 3) * HH + h];
    }
    g[n * HH + h] = acc;
}

// ---------------------------------------------------------------------------
// shared layout (byte offsets, all 16B aligned)
// ---------------------------------------------------------------------------
#define OFF_REL  0          // 65*36*4 = 9360
#define OFF_SL   9360       // 16*32*4 = 2048
#define OFF_SR   11408      // 2048
#define OFF_SC   13456      // 128
#define OFF_OF   13584      // 128
#define OFF_PM   13712      // 256*4 = 1024
#define OFF_PHI  14736      // 256*PITCHB*2 = 20480
#define OFF_PLO  35216      // 20480
#define OFF_WHH  55696      // 32*PITCHB*2 = 2560
#define OFF_WHL  58256      // 2560
#define OFF_WOH  60816      // 64*PITCHB*2 = 5120
#define OFF_WOL  65936      // 5120
#define SMEM_BYTES 71056

// ---------------------------------------------------------------------------
// Fused pair kernel: 16x16-pair tiles, 8 warps, split-bf16 mma.sync pipeline
// ---------------------------------------------------------------------------
__global__ __launch_bounds__(256, 2)
void pair_kernel(const int* __restrict__ resi,
                 const int* __restrict__ chain,
                 const int* __restrict__ batch,
                 const int* __restrict__ mask,
                 const float* __restrict__ W_relpos,
                 const float* __restrict__ ln_scale,
                 const float* __restrict__ ln_offset,
                 const float* __restrict__ W_hidden,
                 const float* __restrict__ W_out,
                 float* __restrict__ out) {
    extern __shared__ __align__(16) unsigned char smraw[];
    float*     sRel = (float*)(smraw + OFF_REL);
    float*     sL   = (float*)(smraw + OFF_SL);
    float*     sR   = (float*)(smraw + OFF_SR);
    float*     sSc  = (float*)(smraw + OFF_SC);
    float*     sOf  = (float*)(smraw + OFF_OF);
    int*       sPM  = (int*)(smraw + OFF_PM);
    uint32_t*  PHI  = (uint32_t*)(smraw + OFF_PHI);
    uint32_t*  PLO  = (uint32_t*)(smraw + OFF_PLO);
    uint32_t*  WHH  = (uint32_t*)(smraw + OFF_WHH);
    uint32_t*  WHL  = (uint32_t*)(smraw + OFF_WHL);
    uint32_t*  WOH  = (uint32_t*)(smraw + OFF_WOH);
    uint32_t*  WOL  = (uint32_t*)(smraw + OFF_WOL);

    const int t    = threadIdx.x;
    const int warp = t >> 5, lane = t & 31;
    const int g    = lane >> 2, tig = lane & 3;
    const int i0   = blockIdx.y * 16, j0 = blockIdx.x * 16;
    const int i    = i0 + (t >> 4), j = j0 + (t & 15);
    const int rbase = warp * 32;

    // ---- per-pair mask; block-level early exit ----
    const bool pm = (batch[i] == batch[j]) && (mask[i] != 0) && (mask[j] != 0);
    sPM[t] = pm;
    const int any = __syncthreads_or((int)pm);

    const float2 z2 = make_float2(0.f, 0.f);
    if (!any) {
#pragma unroll
        for (int mt = 0; mt < 2; ++mt) {
            const int r0 = rbase + mt * 16 + g, r1 = r0 + 8;
            float* p0 = out + ((size_t)((i0 + (r0 >> 4)) * NN + j0 + (r0 & 15))) * OUTS + 2 * tig;
            float* p1 = out + ((size_t)((i0 + (r1 >> 4)) * NN + j0 + (r1 & 15))) * OUTS + 2 * tig;
#pragma unroll
            for (int q = 0; q < 8; ++q) {
                __stcs(reinterpret_cast<float2*>(p0 + 8 * q), z2);
                __stcs(reinterpret_cast<float2*>(p1 + 8 * q), z2);
            }
        }
        return;
    }

    // ---- staging: rel table, L/R tiles, LN params, split-bf16 weights ----
    for (int idx = t; idx < NBINS * HH; idx += 256)
        sRel[(idx >> 5) * 36 + (idx & 31)] = W_relpos[idx];
    for (int idx = t; idx < 16 * HH; idx += 256) {
        sL[idx] = g_left[i0 * HH + idx];
        sR[idx] = g_right[j0 * HH + idx];
    }
    if (t < HH) { sSc[t] = ln_scale[t]; sOf[t] = ln_offset[t]; }
    {
        __nv_bfloat16* whh = (__nv_bfloat16*)WHH;
        __nv_bfloat16* whl = (__nv_bfloat16*)WHL;
        for (int idx = t; idx < HH * HH; idx += 256) {
            int k = idx >> 5, n = idx & 31;
            float w = W_hidden[idx];
            __nv_bfloat16 h = __float2bfloat16_rn(w);
            whh[n * PITCHB + k] = h;
            whl[n * PITCHB + k] = __float2bfloat16_rn(w - __bfloat162float(h));
        }
        __nv_bfloat16* woh = (__nv_bfloat16*)WOH;
        __nv_bfloat16* wol = (__nv_bfloat16*)WOL;
        for (int idx = t; idx < HH * OUTS; idx += 256) {
            int k = idx >> 6, n = idx & 63;
            float w = W_out[idx];
            __nv_bfloat16 h = __float2bfloat16_rn(w);
            woh[n * PITCHB + k] = h;
            wol[n * PITCHB + k] = __float2bfloat16_rn(w - __bfloat162float(h));
        }
    }
    __syncthreads();

    // ---- Phase A: pair build + layernorm -> split-bf16 rows ----
    {
        const bool same_chain = (batch[i] == batch[j]) && (chain[i] == chain[j]);
        int diff = resi[i] - resi[j];
        diff = min(max(diff, -32), 32) + 32;

        const float4* lp = reinterpret_cast<const float4*>(sL + (t >> 4) * HH);
        const float4* rp = reinterpret_cast<const float4*>(sR + (t & 15) * HH);
        const float4* ep = reinterpret_cast<const float4*>(&sRel[diff * 36]);

        float p[HH];
        float mu = 0.f;
#pragma unroll
        for (int h4 = 0; h4 < 8; ++h4) {
            float4 l = lp[h4], r = rp[h4], e = ep[h4];
            float4 v;
            v.x = l.x + r.x; v.y = l.y + r.y; v.z = l.z + r.z; v.w = l.w + r.w;
            if (same_chain) { v.x += e.x; v.y += e.y; v.z += e.z; v.w += e.w; }
            p[h4 * 4 + 0] = v.x; p[h4 * 4 + 1] = v.y;
            p[h4 * 4 + 2] = v.z; p[h4 * 4 + 3] = v.w;
            mu += v.x + v.y + v.z + v.w;
        }
        mu *= (1.f / HH);
        float var = 0.f;
#pragma unroll
        for (int h = 0; h < HH; ++h) { float d = p[h] - mu; var += d * d; }
        var *= (1.f / HH);
        const float rstd = rsqrtf(var + 1e-5f);
#pragma unroll
        for (int k2 = 0; k2 < 16; ++k2) {
            float x0 = (p[2 * k2]     - mu) * rstd * sSc[2 * k2]     + sOf[2 * k2];
            float x1 = (p[2 * k2 + 1] - mu) * rstd * sSc[2 * k2 + 1] + sOf[2 * k2 + 1];
            uint32_t hi, lo;
            split_pack(x0, x1, hi, lo);
            PHI[t * PW + k2] = hi;
            PLO[t * PW + k2] = lo;
        }
    }
    __syncthreads();

    // ---- GEMM1: C[256x32] = P @ Wh  (3-split mma), GELU in registers ----
    float acc1[2][4][4];
#pragma unroll
    for (int mt = 0; mt < 2; ++mt)
#pragma unroll
        for (int nt = 0; nt < 4; ++nt)
#pragma unroll
            for (int e = 0; e < 4; ++e) acc1[mt][nt][e] = 0.f;

#pragma unroll
    for (int kc = 0; kc < 2; ++kc) {
        uint32_t aH[2][4], aL[2][4];
#pragma unroll
        for (int mt = 0; mt < 2; ++mt) {
            const int ro = (rbase + mt * 16 + g) * PW + 8 * kc + tig;
            aH[mt][0] = PHI[ro];       aH[mt][1] = PHI[ro + 8 * PW];
            aH[mt][2] = PHI[ro + 4];   aH[mt][3] = PHI[ro + 8 * PW + 4];
            aL[mt][0] = PLO[ro];       aL[mt][1] = PLO[ro + 8 * PW];
            aL[mt][2] = PLO[ro + 4];   aL[mt][3] = PLO[ro + 8 * PW + 4];
        }
#pragma unroll
        for (int nt = 0; nt < 4; ++nt) {
            const int bo = (8 * nt + g) * PW + 8 * kc + tig;
            uint32_t bh0 = WHH[bo], bh1 = WHH[bo + 4];
            uint32_t bl0 = WHL[bo], bl1 = WHL[bo + 4];
#pragma unroll
            for (int mt = 0; mt < 2; ++mt) {
                mma16816(acc1[mt][nt], aH[mt], bh0, bh1);
                mma16816(acc1[mt][nt], aH[mt], bl0, bl1);
                mma16816(acc1[mt][nt], aL[mt], bh0, bh1);
            }
        }
    }

    // GELU + re-split: C fragments become GEMM2 A fragments directly
    uint32_t hidH[2][2][4], hidL[2][2][4];   // [mt][kc][areg]
#pragma unroll
    for (int mt = 0; mt < 2; ++mt)
#pragma unroll
        for (int nt = 0; nt < 4; ++nt)
#pragma unroll
            for (int e = 0; e < 4; ++e)
                acc1[mt][nt][e] = gelu_tanh(acc1[mt][nt][e]);
#pragma unroll
    for (int mt = 0; mt < 2; ++mt)
#pragma unroll
        for (int kc = 0; kc < 2; ++kc) {
            const int n0 = 2 * kc, n1 = 2 * kc + 1;
            split_pack(acc1[mt][n0][0], acc1[mt][n0][1], hidH[mt][kc][0], hidL[mt][kc][0]);
            split_pack(acc1[mt][n0][2], acc1[mt][n0][3], hidH[mt][kc][1], hidL[mt][kc][1]);
            split_pack(acc1[mt][n1][0], acc1[mt][n1][1], hidH[mt][kc][2], hidL[mt][kc][2]);
            split_pack(acc1[mt][n1][2], acc1[mt][n1][3], hidH[mt][kc][3], hidL[mt][kc][3]);
        }

    // ---- GEMM2: out[256x64] = hid @ Wo, two n-halves of 32 cols ----
#pragma unroll
    for (int half = 0; half < 2; ++half) {
        float acc2[2][4][4];
#pragma unroll
        for (int mt = 0; mt < 2; ++mt)
#pragma unroll
            for (int q = 0; q < 4; ++q)
#pragma unroll
                for (int e = 0; e < 4; ++e) acc2[mt][q][e] = 0.f;

#pragma unroll
        for (int kc = 0; kc < 2; ++kc) {
#pragma unroll
            for (int q = 0; q < 4; ++q) {
                const int nt2 = half * 4 + q;
                const int bo = (8 * nt2 + g) * PW + 8 * kc + tig;
                uint32_t bh0 = WOH[bo], bh1 = WOH[bo + 4];
                uint32_t bl0 = WOL[bo], bl1 = WOL[bo + 4];
#pragma unroll
                for (int mt = 0; mt < 2; ++mt) {
                    mma16816(acc2[mt][q], hidH[mt][kc], bh0, bh1);
                    mma16816(acc2[mt][q], hidH[mt][kc], bl0, bl1);
                    mma16816(acc2[mt][q], hidL[mt][kc], bh0, bh1);
                }
            }
        }

        // stores: row r, cols half*32 + 8q + 2tig (+1) — 8B sector-aligned
#pragma unroll
        for (int mt = 0; mt < 2; ++mt) {
            const int r0 = rbase + mt * 16 + g, r1 = r0 + 8;
            const bool m0 = sPM[r0], m1 = sPM[r1];
            float* p0 = out + ((size_t)((i0 + (r0 >> 4)) * NN + j0 + (r0 & 15))) * OUTS
                            + half * 32 + 2 * tig;
            float* p1 = out + ((size_t)((i0 + (r1 >> 4)) * NN + j0 + (r1 & 15))) * OUTS
                            + half * 32 + 2 * tig;
#pragma unroll
            for (int q = 0; q < 4; ++q) {
                float2 v0 = m0 ? make_float2(acc2[mt][q][0], acc2[mt][q][1]) : z2;
                float2 v1 = m1 ? make_float2(acc2[mt][q][2], acc2[mt][q][3]) : z2;
                __stcs(reinterpret_cast<float2*>(p0 + 8 * q), v0);
                __stcs(reinterpret_cast<float2*>(p1 + 8 * q), v1);
            }
        }
    }
}

// ---------------------------------------------------------------------------
extern "C" void kernel_launch(void* const* d_in, const int* in_sizes, int n_in,
                              void* d_out, int out_size) {
    const float* local = (const float*)d_in[0];
    const int*   resi  = (const int*)d_in[1];
    const int*   chain = (const int*)d_in[2];
    const int*   batch = (const int*)d_in[3];
    const int*   mask  = (const int*)d_in[4];
    const float* Wl    = (const float*)d_in[5];
    const float* Wr    = (const float*)d_in[6];
    const float* Wrel  = (const float*)d_in[7];
    const float* lns   = (const float*)d_in[8];
    const float* lno   = (const float*)d_in[9];
    const float* Wh    = (const float*)d_in[10];
    const float* Wo    = (const float*)d_in[11];
    float*       out   = (float*)d_out;

    static bool attr_set = false;
    if (!attr_set) {
        cudaFuncSetAttribute(pair_kernel,
                             cudaFuncAttributeMaxDynamicSharedMemorySize,
                             SMEM_BYTES);
        attr_set = true;
    }

    proj_kernel<<<256, 256>>>(local, Wl, Wr);

    dim3 grid(NN / 16, NN / 16);
    pair_kernel<<<grid, 256, SMEM_BYTES>>>(resi, chain, batch, mask, Wrel,
                                           lns, lno, Wh, Wo, out);
}

// round 10
// speedup vs baseline: 3.8114x; 1.0048x over previous
#include <cuda_runtime.h>
#include <cuda_bf16.h>
#include <cstdint>

#define NN 1024
#define DD 256
#define HH 32
#define OUTS 64
#define NBINS 65
#define PITCHB 40     // bf16 pitch for fragment arrays
#define PW 20         // pitch in uint32 words (20 mod 32 -> conflict-free frags)

// scratch for projections (device globals: no allocation allowed)
__device__ float g_left[NN * HH];
__device__ float g_right[NN * HH];

// ---------------------------------------------------------------------------
// helpers
// ---------------------------------------------------------------------------
__device__ __forceinline__ uint32_t pack_bf16(float xlo, float xhi) {
    uint32_t r;   // cvt.rn.bf16x2.f32 d, a, b : d.hi=cvt(a), d.lo=cvt(b)
    asm("cvt.rn.bf16x2.f32 %0, %1, %2;" : "=r"(r) : "f"(xhi), "f"(xlo));
    return r;
}
// split x0,x1 into (hi, lo) bf16x2 pairs: x = hi + lo (+O(2^-17))
__device__ __forceinline__ void split_pack(float x0, float x1,
                                           uint32_t& hi, uint32_t& lo) {
    __nv_bfloat16 h0 = __float2bfloat16_rn(x0);
    __nv_bfloat16 h1 = __float2bfloat16_rn(x1);
    float r0 = x0 - __bfloat162float(h0);
    float r1 = x1 - __bfloat162float(h1);
    hi = ((uint32_t)__bfloat16_as_ushort(h1) << 16) | __bfloat16_as_ushort(h0);
    lo = pack_bf16(r0, r1);
}
__device__ __forceinline__ void mma16816(float* c, const uint32_t* a,
                                         uint32_t b0, uint32_t b1) {
    asm("mma.sync.aligned.m16n8k16.row.col.f32.bf16.bf16.f32 "
        "{%0,%1,%2,%3}, {%4,%5,%6,%7}, {%8,%9}, {%0,%1,%2,%3};"
        : "+f"(c[0]), "+f"(c[1]), "+f"(c[2]), "+f"(c[3])
        : "r"(a[0]), "r"(a[1]), "r"(a[2]), "r"(a[3]), "r"(b0), "r"(b1));
}
// JAX approximate (tanh) GELU
__device__ __forceinline__ float gelu_tanh(float x) {
    float u = 0.7978845608028654f * (x + 0.044715f * x * x * x);
    float e = __expf(2.0f * u);
    float t = 1.0f - __fdividef(2.0f, 1.0f + e);
    return 0.5f * x * (1.0f + t);
}

// ---------------------------------------------------------------------------
// Projection: left = local @ W_left, right = local @ W_right [1024,256]@[256,32]
// ---------------------------------------------------------------------------
__global__ void proj_kernel(const float* __restrict__ local,
                            const float* __restrict__ Wl,
                            const float* __restrict__ Wr) {
    int idx  = blockIdx.x * blockDim.x + threadIdx.x;
    int h    = idx & 31;
    int n    = (idx >> 5) & (NN - 1);
    int side = idx >> 15;
    const float* W = side ? Wr : Wl;
    float*       g = side ? g_right : g_left;

    const float4* row4 = reinterpret_cast<const float4*>(local + (size_t)n * DD);
    float acc = 0.f;
#pragma unroll
    for (int d4 = 0; d4 < DD / 4; ++d4) {
        float4 r = row4[d4];
        int d = d4 * 4;
        acc += r.x * W[(d + 0) * HH + h];
        acc += r.y * W[(d + 1) * HH + h];
        acc += r.z * W[(d + 2) * HH + h];
        acc += r.w * W[(d + 3) * HH + h];
    }
    g[n * HH + h] = acc;
}

// ---------------------------------------------------------------------------
// shared layout (byte offsets, all 16B aligned)
// ---------------------------------------------------------------------------
#define OFF_REL  0          // 65*36*4 = 9360
#define OFF_SL   9360       // 16*32*4 = 2048
#define OFF_SR   11408      // 2048
#define OFF_SC   13456      // 128
#define OFF_OF   13584      // 128
#define OFF_PM   13712      // 256*4 = 1024
#define OFF_PHI  14736      // 256*PITCHB*2 = 20480
#define OFF_PLO  35216      // 20480
#define OFF_WHH  55696      // 32*PITCHB*2 = 2560
#define OFF_WHL  58256      // 2560
#define OFF_WOH  60816      // 64*PITCHB*2 = 5120
#define OFF_WOL  65936      // 5120
#define SMEM_BYTES 71056

// ---------------------------------------------------------------------------
// Fused pair kernel: 16x16-pair tiles, 8 warps, split-bf16 mma.sync pipeline
// ---------------------------------------------------------------------------
__global__ __launch_bounds__(256, 2)
void pair_kernel(const int* __restrict__ resi,
                 const int* __restrict__ chain,
                 const int* __restrict__ batch,
                 const int* __restrict__ mask,
                 const float* __restrict__ W_relpos,
                 const float* __restrict__ ln_scale,
                 const float* __restrict__ ln_offset,
                 const float* __restrict__ W_hidden,
                 const float* __restrict__ W_out,
                 float* __restrict__ out) {
    extern __shared__ __align__(16) unsigned char smraw[];
    float*     sRel = (float*)(smraw + OFF_REL);
    float*     sL   = (float*)(smraw + OFF_SL);
    float*     sR   = (float*)(smraw + OFF_SR);
    float*     sSc  = (float*)(smraw + OFF_SC);
    float*     sOf  = (float*)(smraw + OFF_OF);
    int*       sPM  = (int*)(smraw + OFF_PM);
    uint32_t*  PHI  = (uint32_t*)(smraw + OFF_PHI);
    uint32_t*  PLO  = (uint32_t*)(smraw + OFF_PLO);
    uint32_t*  WHH  = (uint32_t*)(smraw + OFF_WHH);
    uint32_t*  WHL  = (uint32_t*)(smraw + OFF_WHL);
    uint32_t*  WOH  = (uint32_t*)(smraw + OFF_WOH);
    uint32_t*  WOL  = (uint32_t*)(smraw + OFF_WOL);

    const int t    = threadIdx.x;
    const int warp = t >> 5, lane = t & 31;
    const int g    = lane >> 2, tig = lane & 3;
    const int i0   = blockIdx.y * 16, j0 = blockIdx.x * 16;
    const int i    = i0 + (t >> 4), j = j0 + (t & 15);
    const int rbase = warp * 32;

    // ---- per-pair mask; block-level early exit ----
    const bool pm = (batch[i] == batch[j]) && (mask[i] != 0) && (mask[j] != 0);
    sPM[t] = pm;
    const int any = __syncthreads_or((int)pm);

    const float2 z2 = make_float2(0.f, 0.f);
    if (!any) {
#pragma unroll
        for (int mt = 0; mt < 2; ++mt) {
            const int r0 = rbase + mt * 16 + g, r1 = r0 + 8;
            float* p0 = out + ((size_t)((i0 + (r0 >> 4)) * NN + j0 + (r0 & 15))) * OUTS + 2 * tig;
            float* p1 = out + ((size_t)((i0 + (r1 >> 4)) * NN + j0 + (r1 & 15))) * OUTS + 2 * tig;
#pragma unroll
            for (int q = 0; q < 8; ++q) {
                __stcs(reinterpret_cast<float2*>(p0 + 8 * q), z2);
                __stcs(reinterpret_cast<float2*>(p1 + 8 * q), z2);
            }
        }
        return;
    }

    // ---- staging: rel table, L/R tiles, LN params, split-bf16 weights ----
    for (int idx = t; idx < NBINS * HH; idx += 256)
        sRel[(idx >> 5) * 36 + (idx & 31)] = W_relpos[idx];
    for (int idx = t; idx < 16 * HH; idx += 256) {
        sL[idx] = g_left[i0 * HH + idx];
        sR[idx] = g_right[j0 * HH + idx];
    }
    if (t < HH) { sSc[t] = ln_scale[t]; sOf[t] = ln_offset[t]; }
    {
        __nv_bfloat16* whh = (__nv_bfloat16*)WHH;
        __nv_bfloat16* whl = (__nv_bfloat16*)WHL;
        for (int idx = t; idx < HH * HH; idx += 256) {
            int k = idx >> 5, n = idx & 31;
            float w = W_hidden[idx];
            __nv_bfloat16 h = __float2bfloat16_rn(w);
            whh[n * PITCHB + k] = h;
            whl[n * PITCHB + k] = __float2bfloat16_rn(w - __bfloat162float(h));
        }
        __nv_bfloat16* woh = (__nv_bfloat16*)WOH;
        __nv_bfloat16* wol = (__nv_bfloat16*)WOL;
        for (int idx = t; idx < HH * OUTS; idx += 256) {
            int k = idx >> 6, n = idx & 63;
            float w = W_out[idx];
            __nv_bfloat16 h = __float2bfloat16_rn(w);
            woh[n * PITCHB + k] = h;
            wol[n * PITCHB + k] = __float2bfloat16_rn(w - __bfloat162float(h));
        }
    }
    __syncthreads();

    // ---- Phase A: pair build + layernorm -> split-bf16 rows ----
    {
        const bool same_chain = (batch[i] == batch[j]) && (chain[i] == chain[j]);
        int diff = resi[i] - resi[j];
        diff = min(max(diff, -32), 32) + 32;

        const float4* lp = reinterpret_cast<const float4*>(sL + (t >> 4) * HH);
        const float4* rp = reinterpret_cast<const float4*>(sR + (t & 15) * HH);
        const float4* ep = reinterpret_cast<const float4*>(&sRel[diff * 36]);

        float p[HH];
        float mu = 0.f;
#pragma unroll
        for (int h4 = 0; h4 < 8; ++h4) {
            float4 l = lp[h4], r = rp[h4], e = ep[h4];
            float4 v;
            v.x = l.x + r.x; v.y = l.y + r.y; v.z = l.z + r.z; v.w = l.w + r.w;
            if (same_chain) { v.x += e.x; v.y += e.y; v.z += e.z; v.w += e.w; }
            p[h4 * 4 + 0] = v.x; p[h4 * 4 + 1] = v.y;
            p[h4 * 4 + 2] = v.z; p[h4 * 4 + 3] = v.w;
            mu += v.x + v.y + v.z + v.w;
        }
        mu *= (1.f / HH);
        float var = 0.f;
#pragma unroll
        for (int h = 0; h < HH; ++h) { float d = p[h] - mu; var += d * d; }
        var *= (1.f / HH);
        const float rstd = rsqrtf(var + 1e-5f);
#pragma unroll
        for (int k2 = 0; k2 < 16; ++k2) {
            float x0 = (p[2 * k2]     - mu) * rstd * sSc[2 * k2]     + sOf[2 * k2];
            float x1 = (p[2 * k2 + 1] - mu) * rstd * sSc[2 * k2 + 1] + sOf[2 * k2 + 1];
            uint32_t hi, lo;
            split_pack(x0, x1, hi, lo);
            PHI[t * PW + k2] = hi;
            PLO[t * PW + k2] = lo;
        }
    }
    __syncthreads();

    // ---- GEMM1: C[256x32] = P @ Wh  (3-split mma), GELU in registers ----
    float acc1[2][4][4];
#pragma unroll
    for (int mt = 0; mt < 2; ++mt)
#pragma unroll
        for (int nt = 0; nt < 4; ++nt)
#pragma unroll
            for (int e = 0; e < 4; ++e) acc1[mt][nt][e] = 0.f;

#pragma unroll
    for (int kc = 0; kc < 2; ++kc) {
        uint32_t aH[2][4], aL[2][4];
#pragma unroll
        for (int mt = 0; mt < 2; ++mt) {
            const int ro = (rbase + mt * 16 + g) * PW + 8 * kc + tig;
            aH[mt][0] = PHI[ro];       aH[mt][1] = PHI[ro + 8 * PW];
            aH[mt][2] = PHI[ro + 4];   aH[mt][3] = PHI[ro + 8 * PW + 4];
            aL[mt][0] = PLO[ro];       aL[mt][1] = PLO[ro + 8 * PW];
            aL[mt][2] = PLO[ro + 4];   aL[mt][3] = PLO[ro + 8 * PW + 4];
        }
#pragma unroll
        for (int nt = 0; nt < 4; ++nt) {
            const int bo = (8 * nt + g) * PW + 8 * kc + tig;
            uint32_t bh0 = WHH[bo], bh1 = WHH[bo + 4];
            uint32_t bl0 = WHL[bo], bl1 = WHL[bo + 4];
#pragma unroll
            for (int mt = 0; mt < 2; ++mt) {
                mma16816(acc1[mt][nt], aH[mt], bh0, bh1);
                mma16816(acc1[mt][nt], aH[mt], bl0, bl1);
                mma16816(acc1[mt][nt], aL[mt], bh0, bh1);
            }
        }
    }

    // GELU + re-split: C fragments become GEMM2 A fragments directly
    uint32_t hidH[2][2][4], hidL[2][2][4];   // [mt][kc][areg]
#pragma unroll
    for (int mt = 0; mt < 2; ++mt)
#pragma unroll
        for (int nt = 0; nt < 4; ++nt)
#pragma unroll
            for (int e = 0; e < 4; ++e)
                acc1[mt][nt][e] = gelu_tanh(acc1[mt][nt][e]);
#pragma unroll
    for (int mt = 0; mt < 2; ++mt)
#pragma unroll
        for (int kc = 0; kc < 2; ++kc) {
            const int n0 = 2 * kc, n1 = 2 * kc + 1;
            split_pack(acc1[mt][n0][0], acc1[mt][n0][1], hidH[mt][kc][0], hidL[mt][kc][0]);
            split_pack(acc1[mt][n0][2], acc1[mt][n0][3], hidH[mt][kc][1], hidL[mt][kc][1]);
            split_pack(acc1[mt][n1][0], acc1[mt][n1][1], hidH[mt][kc][2], hidL[mt][kc][2]);
            split_pack(acc1[mt][n1][2], acc1[mt][n1][3], hidH[mt][kc][3], hidL[mt][kc][3]);
        }

    // ---- GEMM2: out[256x64] = hid @ Wo, two n-halves of 32 cols ----
#pragma unroll
    for (int half = 0; half < 2; ++half) {
        float acc2[2][4][4];
#pragma unroll
        for (int mt = 0; mt < 2; ++mt)
#pragma unroll
            for (int q = 0; q < 4; ++q)
#pragma unroll
                for (int e = 0; e < 4; ++e) acc2[mt][q][e] = 0.f;

#pragma unroll
        for (int kc = 0; kc < 2; ++kc) {
#pragma unroll
            for (int q = 0; q < 4; ++q) {
                const int nt2 = half * 4 + q;
                const int bo = (8 * nt2 + g) * PW + 8 * kc + tig;
                uint32_t bh0 = WOH[bo], bh1 = WOH[bo + 4];
                uint32_t bl0 = WOL[bo], bl1 = WOL[bo + 4];
#pragma unroll
                for (int mt = 0; mt < 2; ++mt) {
                    mma16816(acc2[mt][q], hidH[mt][kc], bh0, bh1);
                    mma16816(acc2[mt][q], hidH[mt][kc], bl0, bl1);
                    mma16816(acc2[mt][q], hidL[mt][kc], bh0, bh1);
                }
            }
        }

        // stores: row r, cols half*32 + 8q + 2tig (+1) — 8B sector-aligned
#pragma unroll
        for (int mt = 0; mt < 2; ++mt) {
            const int r0 = rbase + mt * 16 + g, r1 = r0 + 8;
            const bool m0 = sPM[r0], m1 = sPM[r1];
            float* p0 = out + ((size_t)((i0 + (r0 >> 4)) * NN + j0 + (r0 & 15))) * OUTS
                            + half * 32 + 2 * tig;
            float* p1 = out + ((size_t)((i0 + (r1 >> 4)) * NN + j0 + (r1 & 15))) * OUTS
                            + half * 32 + 2 * tig;
#pragma unroll
            for (int q = 0; q < 4; ++q) {
                float2 v0 = m0 ? make_float2(acc2[mt][q][0], acc2[mt][q][1]) : z2;
                float2 v1 = m1 ? make_float2(acc2[mt][q][2], acc2[mt][q][3]) : z2;
                __stcs(reinterpret_cast<float2*>(p0 + 8 * q), v0);
                __stcs(reinterpret_cast<float2*>(p1 + 8 * q), v1);
            }
        }
    }
}

// ---------------------------------------------------------------------------
extern "C" void kernel_launch(void* const* d_in, const int* in_sizes, int n_in,
                              void* d_out, int out_size) {
    const float* local = (const float*)d_in[0];
    const int*   resi  = (const int*)d_in[1];
    const int*   chain = (const int*)d_in[2];
    const int*   batch = (const int*)d_in[3];
    const int*   mask  = (const int*)d_in[4];
    const float* Wl    = (const float*)d_in[5];
    const float* Wr    = (const float*)d_in[6];
    const float* Wrel  = (const float*)d_in[7];
    const float* lns   = (const float*)d_in[8];
    const float* lno   = (const float*)d_in[9];
    const float* Wh    = (const float*)d_in[10];
    const float* Wo    = (const float*)d_in[11];
    float*       out   = (float*)d_out;

    static bool attr_set = false;
    if (!attr_set) {
        cudaFuncSetAttribute(pair_kernel,
                             cudaFuncAttributeMaxDynamicSharedMemorySize,
                             SMEM_BYTES);
        attr_set = true;
    }

    proj_kernel<<<256, 256>>>(local, Wl, Wr);

    dim3 grid(NN / 16, NN / 16);
    pair_kernel<<<grid, 256, SMEM_BYTES>>>(resi, chain, batch, mask, Wrel,
                                           lns, lno, Wh, Wo, out);
}

// round 11
// speedup vs baseline: 4.1791x; 1.0965x over previous
#include <cuda_runtime.h>
#include <cuda_bf16.h>
#include <cstdint>

#define NN 1024
#define DD 256
#define HH 32
#define OUTS 64
#define NBINS 65
#define PITCHB 40     // bf16 pitch for fragment arrays (80B rows: bank-perfect LDSM)
#define PW 20         // pitch in uint32 words

// scratch for projections (device globals: no allocation allowed)
__device__ float g_left[NN * HH];
__device__ float g_right[NN * HH];
// precomputed split-bf16 weights, exact smem image: WhH|WhL|WoH|WoL (15360 B)
__device__ __align__(16) unsigned char g_wpack[15360];

// ---------------------------------------------------------------------------
// helpers
// ---------------------------------------------------------------------------
__device__ __forceinline__ uint32_t pack_bf16(float xlo, float xhi) {
    uint32_t r;
    asm("cvt.rn.bf16x2.f32 %0, %1, %2;" : "=r"(r) : "f"(xhi), "f"(xlo));
    return r;
}
__device__ __forceinline__ void split_pack(float x0, float x1,
                                           uint32_t& hi, uint32_t& lo) {
    __nv_bfloat16 h0 = __float2bfloat16_rn(x0);
    __nv_bfloat16 h1 = __float2bfloat16_rn(x1);
    float r0 = x0 - __bfloat162float(h0);
    float r1 = x1 - __bfloat162float(h1);
    hi = ((uint32_t)__bfloat16_as_ushort(h1) << 16) | __bfloat16_as_ushort(h0);
    lo = pack_bf16(r0, r1);
}
__device__ __forceinline__ void mma16816(float* c, const uint32_t* a,
                                         uint32_t b0, uint32_t b1) {
    asm("mma.sync.aligned.m16n8k16.row.col.f32.bf16.bf16.f32 "
        "{%0,%1,%2,%3}, {%4,%5,%6,%7}, {%8,%9}, {%0,%1,%2,%3};"
        : "+f"(c[0]), "+f"(c[1]), "+f"(c[2]), "+f"(c[3])
        : "r"(a[0]), "r"(a[1]), "r"(a[2]), "r"(a[3]), "r"(b0), "r"(b1));
}
__device__ __forceinline__ void ldsm_x4(uint32_t* r, uint32_t addr) {
    asm volatile("ldmatrix.sync.aligned.m8n8.x4.shared.b16 {%0,%1,%2,%3}, [%4];"
                 : "=r"(r[0]), "=r"(r[1]), "=r"(r[2]), "=r"(r[3]) : "r"(addr));
}
__device__ __forceinline__ float gelu_tanh(float x) {
    float u = 0.7978845608028654f * (x + 0.044715f * x * x * x);
    float e = __expf(2.0f * u);
    float t = 1.0f - __fdividef(2.0f, 1.0f + e);
    return 0.5f * x * (1.0f + t);
}

// ---------------------------------------------------------------------------
// Projection: left = local @ W_left, right = local @ W_right [1024,256]@[256,32]
// ---------------------------------------------------------------------------
__global__ void proj_kernel(const float* __restrict__ local,
                            const float* __restrict__ Wl,
                            const float* __restrict__ Wr) {
    int idx  = blockIdx.x * blockDim.x + threadIdx.x;
    int h    = idx & 31;
    int n    = (idx >> 5) & (NN - 1);
    int side = idx >> 15;
    const float* W = side ? Wr : Wl;
    float*       g = side ? g_right : g_left;

    const float4* row4 = reinterpret_cast<const float4*>(local + (size_t)n * DD);
    float acc = 0.f;
#pragma unroll
    for (int d4 = 0; d4 < DD / 4; ++d4) {
        float4 r = row4[d4];
        int d = d4 * 4;
        acc += r.x * W[(d + 0) * HH + h];
        acc += r.y * W[(d + 1) * HH + h];
        acc += r.z * W[(d + 2) * HH + h];
        acc += r.w * W[(d + 3) * HH + h];
    }
    g[n * HH + h] = acc;
}

// ---------------------------------------------------------------------------
// Weight prep: split-bf16 conversion once, into smem-image layout
// bf16 elems: [0,1280) WhH ; [1280,2560) WhL ; [2560,5120) WoH ; [5120,7680) WoL
// rows n-major, PITCHB=40 bf16 per row, k in [0,32) real, rest zero pad
// ---------------------------------------------------------------------------
__global__ void prep_kernel(const float* __restrict__ Wh,
                            const float* __restrict__ Wo) {
    int t = blockIdx.x * blockDim.x + threadIdx.x;   // 0..3839
    __nv_bfloat16* dst = (__nv_bfloat16*)g_wpack;
    if (t < 32 * PITCHB) {
        int n = t / PITCHB, k = t % PITCHB;
        float w = (k < HH) ? Wh[k * HH + n] : 0.f;
        __nv_bfloat16 h = __float2bfloat16_rn(w);
        dst[t]        = h;
        dst[1280 + t] = __float2bfloat16_rn(w - __bfloat162float(h));
    } else if (t < 32 * PITCHB + 64 * PITCHB) {
        int u = t - 32 * PITCHB;
        int n = u / PITCHB, k = u % PITCHB;
        float w = (k < HH) ? Wo[k * OUTS + n] : 0.f;
        __nv_bfloat16 h = __float2bfloat16_rn(w);
        dst[2560 + u] = h;
        dst[5120 + u] = __float2bfloat16_rn(w - __bfloat162float(h));
    }
}

// ---------------------------------------------------------------------------
// shared layout (byte offsets, all 16B aligned)
// ---------------------------------------------------------------------------
#define OFF_REL  0          // 65*36*4 = 9360
#define OFF_SL   9360       // 2048
#define OFF_SR   11408      // 2048
#define OFF_SC   13456      // 128
#define OFF_OF   13584      // 128
#define OFF_PM   13712      // 1024
#define OFF_PHI  14736      // 20480
#define OFF_PLO  35216      // 20480
#define OFF_WHH  55696      // 2560
#define OFF_WHL  58256      // 2560
#define OFF_WOH  60816      // 5120
#define OFF_WOL  65936      // 5120
#define SMEM_BYTES 71056

// ---------------------------------------------------------------------------
// Fused pair kernel: 16x16-pair tiles, 8 warps, split-bf16 mma + ldmatrix
// ---------------------------------------------------------------------------
__global__ __launch_bounds__(256, 2)
void pair_kernel(const int* __restrict__ resi,
                 const int* __restrict__ chain,
                 const int* __restrict__ batch,
                 const int* __restrict__ mask,
                 const float* __restrict__ W_relpos,
                 const float* __restrict__ ln_scale,
                 const float* __restrict__ ln_offset,
                 float* __restrict__ out) {
    extern __shared__ __align__(16) unsigned char smraw[];
    float*     sRel = (float*)(smraw + OFF_REL);
    float*     sL   = (float*)(smraw + OFF_SL);
    float*     sR   = (float*)(smraw + OFF_SR);
    float*     sSc  = (float*)(smraw + OFF_SC);
    float*     sOf  = (float*)(smraw + OFF_OF);
    int*       sPM  = (int*)(smraw + OFF_PM);
    uint32_t*  PHI  = (uint32_t*)(smraw + OFF_PHI);
    uint32_t*  PLO  = (uint32_t*)(smraw + OFF_PLO);

    const int t    = threadIdx.x;
    const int warp = t >> 5, lane = t & 31;
    const int g    = lane >> 2, tig = lane & 3;
    const int i0   = blockIdx.y * 16, j0 = blockIdx.x * 16;
    const int i    = i0 + (t >> 4), j = j0 + (t & 15);
    const int rbase = warp * 32;

    // ---- per-pair mask; block-level early exit ----
    const bool pm = (batch[i] == batch[j]) && (mask[i] != 0) && (mask[j] != 0);
    sPM[t] = pm;
    const int any = __syncthreads_or((int)pm);

    const float2 z2 = make_float2(0.f, 0.f);
    if (!any) {
#pragma unroll
        for (int mt = 0; mt < 2; ++mt) {
            const int r0 = rbase + mt * 16 + g, r1 = r0 + 8;
            float* p0 = out + ((size_t)((i0 + (r0 >> 4)) * NN + j0 + (r0 & 15))) * OUTS + 2 * tig;
            float* p1 = out + ((size_t)((i0 + (r1 >> 4)) * NN + j0 + (r1 & 15))) * OUTS + 2 * tig;
#pragma unroll
            for (int q = 0; q < 8; ++q) {
                __stcs(reinterpret_cast<float2*>(p0 + 8 * q), z2);
                __stcs(reinterpret_cast<float2*>(p1 + 8 * q), z2);
            }
        }
        return;
    }

    // ---- staging: rel table, L/R tiles, LN params, prepacked weights ----
    for (int idx = t; idx < NBINS * HH; idx += 256)
        sRel[(idx >> 5) * 36 + (idx & 31)] = W_relpos[idx];
    for (int idx = t; idx < 16 * HH; idx += 256) {
        sL[idx] = g_left[i0 * HH + idx];
        sR[idx] = g_right[j0 * HH + idx];
    }
    if (t < HH) { sSc[t] = ln_scale[t]; sOf[t] = ln_offset[t]; }
    {
        const uint4* src = (const uint4*)g_wpack;
        uint4* dst = (uint4*)(smraw + OFF_WHH);
#pragma unroll
        for (int idx = t; idx < 960; idx += 256) dst[idx] = src[idx];
    }
    __syncthreads();

    // ---- Phase A: pair build + layernorm -> split-bf16 rows ----
    {
        const bool same_chain = (batch[i] == batch[j]) && (chain[i] == chain[j]);
        int diff = resi[i] - resi[j];
        diff = min(max(diff, -32), 32) + 32;

        const float4* lp = reinterpret_cast<const float4*>(sL + (t >> 4) * HH);
        const float4* rp = reinterpret_cast<const float4*>(sR + (t & 15) * HH);
        const float4* ep = reinterpret_cast<const float4*>(&sRel[diff * 36]);

        float p[HH];
        float mu = 0.f;
#pragma unroll
        for (int h4 = 0; h4 < 8; ++h4) {
            float4 l = lp[h4], r = rp[h4], e = ep[h4];
            float4 v;
            v.x = l.x + r.x; v.y = l.y + r.y; v.z = l.z + r.z; v.w = l.w + r.w;
            if (same_chain) { v.x += e.x; v.y += e.y; v.z += e.z; v.w += e.w; }
            p[h4 * 4 + 0] = v.x; p[h4 * 4 + 1] = v.y;
            p[h4 * 4 + 2] = v.z; p[h4 * 4 + 3] = v.w;
            mu += v.x + v.y + v.z + v.w;
        }
        mu *= (1.f / HH);
        float var = 0.f;
#pragma unroll
        for (int h = 0; h < HH; ++h) { float d = p[h] - mu; var += d * d; }
        var *= (1.f / HH);
        const float rstd = rsqrtf(var + 1e-5f);

        uint32_t hiw[16], low[16];
#pragma unroll
        for (int k2 = 0; k2 < 16; ++k2) {
            float x0 = (p[2 * k2]     - mu) * rstd * sSc[2 * k2]     + sOf[2 * k2];
            float x1 = (p[2 * k2 + 1] - mu) * rstd * sSc[2 * k2 + 1] + sOf[2 * k2 + 1];
            split_pack(x0, x1, hiw[k2], low[k2]);
        }
        uint4* ph = reinterpret_cast<uint4*>(&PHI[t * PW]);
        uint4* pl = reinterpret_cast<uint4*>(&PLO[t * PW]);
#pragma unroll
        for (int q = 0; q < 4; ++q) {
            ph[q] = make_uint4(hiw[4 * q], hiw[4 * q + 1], hiw[4 * q + 2], hiw[4 * q + 3]);
            pl[q] = make_uint4(low[4 * q], low[4 * q + 1], low[4 * q + 2], low[4 * q + 3]);
        }
    }
    __syncthreads();

    // ---- ldmatrix base addresses (32-bit shared space) ----
    const uint32_t sbase = (uint32_t)__cvta_generic_to_shared(smraw);
    // A: row = rbase + (lane&15), k-half = lane>>4
    const uint32_t aBase = sbase + OFF_PHI +
        (uint32_t)(((rbase + (lane & 15)) * PW + (lane >> 4) * 4) << 2);
    // B: n-row = 8*(lane>>4) + (lane&7), k-half = (lane>>3)&1
    const uint32_t bRow = (uint32_t)((8 * (lane >> 4) + (lane & 7)) * 80 +
                                     ((lane >> 3) & 1) * 16);
    const uint32_t b1Base = sbase + OFF_WHH + bRow;
    const uint32_t b2Base = sbase + OFF_WOH + bRow;

    // ---- GEMM1: C[256x32] = P @ Wh  (3-split mma), GELU in registers ----
    float acc1[2][4][4];
#pragma unroll
    for (int mt = 0; mt < 2; ++mt)
#pragma unroll
        for (int nt = 0; nt < 4; ++nt)
#pragma unroll
            for (int e = 0; e < 4; ++e) acc1[mt][nt][e] = 0.f;

#pragma unroll
    for (int kc = 0; kc < 2; ++kc) {
        uint32_t aH[2][4], aL[2][4];
        ldsm_x4(aH[0], aBase + kc * 32);
        ldsm_x4(aH[1], aBase + 1280 + kc * 32);
        ldsm_x4(aL[0], aBase + 20480 + kc * 32);
        ldsm_x4(aL[1], aBase + 20480 + 1280 + kc * 32);
        uint32_t bH[2][4], bL[2][4];
        ldsm_x4(bH[0], b1Base + kc * 32);            // nt 0,1 hi
        ldsm_x4(bH[1], b1Base + 1280 + kc * 32);     // nt 2,3 hi
        ldsm_x4(bL[0], b1Base + 2560 + kc * 32);     // nt 0,1 lo
        ldsm_x4(bL[1], b1Base + 3840 + kc * 32);     // nt 2,3 lo
#pragma unroll
        for (int nt = 0; nt < 4; ++nt) {
            const uint32_t bh0 = bH[nt >> 1][(nt & 1) * 2];
            const uint32_t bh1 = bH[nt >> 1][(nt & 1) * 2 + 1];
            const uint32_t bl0 = bL[nt >> 1][(nt & 1) * 2];
            const uint32_t bl1 = bL[nt >> 1][(nt & 1) * 2 + 1];
#pragma unroll
            for (int mt = 0; mt < 2; ++mt) {
                mma16816(acc1[mt][nt], aH[mt], bh0, bh1);
                mma16816(acc1[mt][nt], aH[mt], bl0, bl1);
                mma16816(acc1[mt][nt], aL[mt], bh0, bh1);
            }
        }
    }

    // GELU + re-split: C fragments become GEMM2 A fragments directly
    uint32_t hidH[2][2][4], hidL[2][2][4];   // [mt][kc][areg]
#pragma unroll
    for (int mt = 0; mt < 2; ++mt)
#pragma unroll
        for (int nt = 0; nt < 4; ++nt)
#pragma unroll
            for (int e = 0; e < 4; ++e)
                acc1[mt][nt][e] = gelu_tanh(acc1[mt][nt][e]);
#pragma unroll
    for (int mt = 0; mt < 2; ++mt)
#pragma unroll
        for (int kc = 0; kc < 2; ++kc) {
            const int n0 = 2 * kc, n1 = 2 * kc + 1;
            split_pack(acc1[mt][n0][0], acc1[mt][n0][1], hidH[mt][kc][0], hidL[mt][kc][0]);
            split_pack(acc1[mt][n0][2], acc1[mt][n0][3], hidH[mt][kc][1], hidL[mt][kc][1]);
            split_pack(acc1[mt][n1][0], acc1[mt][n1][1], hidH[mt][kc][2], hidL[mt][kc][2]);
            split_pack(acc1[mt][n1][2], acc1[mt][n1][3], hidH[mt][kc][3], hidL[mt][kc][3]);
        }

    // ---- GEMM2: out[256x64] = hid @ Wo, two n-halves of 32 cols ----
#pragma unroll
    for (int half = 0; half < 2; ++half) {
        float acc2[2][4][4];
#pragma unroll
        for (int mt = 0; mt < 2; ++mt)
#pragma unroll
            for (int q = 0; q < 4; ++q)
#pragma unroll
                for (int e = 0; e < 4; ++e) acc2[mt][q][e] = 0.f;

#pragma unroll
        for (int kc = 0; kc < 2; ++kc) {
#pragma unroll
            for (int p = 0; p < 2; ++p) {    // nt2 pair {half*4+2p, +1}
                uint32_t bh[4], bl[4];
                ldsm_x4(bh, b2Base + (half * 2 + p) * 1280 + kc * 32);
                ldsm_x4(bl, b2Base + 5120 + (half * 2 + p) * 1280 + kc * 32);
#pragma unroll
                for (int mt = 0; mt < 2; ++mt) {
                    mma16816(acc2[mt][2 * p],     hidH[mt][kc], bh[0], bh[1]);
                    mma16816(acc2[mt][2 * p],     hidH[mt][kc], bl[0], bl[1]);
                    mma16816(acc2[mt][2 * p],     hidL[mt][kc], bh[0], bh[1]);
                    mma16816(acc2[mt][2 * p + 1], hidH[mt][kc], bh[2], bh[3]);
                    mma16816(acc2[mt][2 * p + 1], hidH[mt][kc], bl[2], bl[3]);
                    mma16816(acc2[mt][2 * p + 1], hidL[mt][kc], bh[2], bh[3]);
                }
            }
        }

        // stores: row r, cols half*32 + 8q + 2tig (+1) — 8B sector-aligned
#pragma unroll
        for (int mt = 0; mt < 2; ++mt) {
            const int r0 = rbase + mt * 16 + g, r1 = r0 + 8;
            const bool m0 = sPM[r0], m1 = sPM[r1];
            float* p0 = out + ((size_t)((i0 + (r0 >> 4)) * NN + j0 + (r0 & 15))) * OUTS
                            + half * 32 + 2 * tig;
            float* p1 = out + ((size_t)((i0 + (r1 >> 4)) * NN + j0 + (r1 & 15))) * OUTS
                            + half * 32 + 2 * tig;
#pragma unroll
            for (int q = 0; q < 4; ++q) {
                float2 v0 = m0 ? make_float2(acc2[mt][q][0], acc2[mt][q][1]) : z2;
                float2 v1 = m1 ? make_float2(acc2[mt][q][2], acc2[mt][q][3]) : z2;
                __stcs(reinterpret_cast<float2*>(p0 + 8 * q), v0);
                __stcs(reinterpret_cast<float2*>(p1 + 8 * q), v1);
            }
        }
    }
}

// ---------------------------------------------------------------------------
extern "C" void kernel_launch(void* const* d_in, const int* in_sizes, int n_in,
                              void* d_out, int out_size) {
    const float* local = (const float*)d_in[0];
    const int*   resi  = (const int*)d_in[1];
    const int*   chain = (const int*)d_in[2];
    const int*   batch = (const int*)d_in[3];
    const int*   mask  = (const int*)d_in[4];
    const float* Wl    = (const float*)d_in[5];
    const float* Wr    = (const float*)d_in[6];
    const float* Wrel  = (const float*)d_in[7];
    const float* lns   = (const float*)d_in[8];
    const float* lno   = (const float*)d_in[9];
    const float* Wh    = (const float*)d_in[10];
    const float* Wo    = (const float*)d_in[11];
    float*       out   = (float*)d_out;

    static bool attr_set = false;
    if (!attr_set) {
        cudaFuncSetAttribute(pair_kernel,
                             cudaFuncAttributeMaxDynamicSharedMemorySize,
                             SMEM_BYTES);
        attr_set = true;
    }

    proj_kernel<<<256, 256>>>(local, Wl, Wr);
    prep_kernel<<<15, 256>>>(Wh, Wo);

    dim3 grid(NN / 16, NN / 16);
    pair_kernel<<<grid, 256, SMEM_BYTES>>>(resi, chain, batch, mask, Wrel,
                                           lns, lno, out);
}

// round 12
// speedup vs baseline: 4.3377x; 1.0380x over previous
#include <cuda_runtime.h>
#include <cuda_bf16.h>
#include <cstdint>

#define NN 1024
#define DD 256
#define HH 32
#define OUTS 64
#define NBINS 65
#define PITCHB 40     // bf16 pitch for fragment arrays (80B rows: bank-perfect LDSM)
#define PW 20         // pitch in uint32 words

// scratch for projections (device globals: no allocation allowed)
__device__ float g_left[NN * HH];
__device__ float g_right[NN * HH];
// precomputed split-bf16 weights, exact smem image: WhH|WhL|WoH|WoL (15360 B)
__device__ __align__(16) unsigned char g_wpack[15360];

// ---------------------------------------------------------------------------
// helpers
// ---------------------------------------------------------------------------
__device__ __forceinline__ uint32_t pack_bf16(float xlo, float xhi) {
    uint32_t r;
    asm("cvt.rn.bf16x2.f32 %0, %1, %2;" : "=r"(r) : "f"(xhi), "f"(xlo));
    return r;
}
__device__ __forceinline__ void split_pack(float x0, float x1,
                                           uint32_t& hi, uint32_t& lo) {
    __nv_bfloat16 h0 = __float2bfloat16_rn(x0);
    __nv_bfloat16 h1 = __float2bfloat16_rn(x1);
    float r0 = x0 - __bfloat162float(h0);
    float r1 = x1 - __bfloat162float(h1);
    hi = ((uint32_t)__bfloat16_as_ushort(h1) << 16) | __bfloat16_as_ushort(h0);
    lo = pack_bf16(r0, r1);
}
__device__ __forceinline__ void mma16816(float* c, const uint32_t* a,
                                         uint32_t b0, uint32_t b1) {
    asm("mma.sync.aligned.m16n8k16.row.col.f32.bf16.bf16.f32 "
        "{%0,%1,%2,%3}, {%4,%5,%6,%7}, {%8,%9}, {%0,%1,%2,%3};"
        : "+f"(c[0]), "+f"(c[1]), "+f"(c[2]), "+f"(c[3])
        : "r"(a[0]), "r"(a[1]), "r"(a[2]), "r"(a[3]), "r"(b0), "r"(b1));
}
__device__ __forceinline__ void ldsm_x4(uint32_t* r, uint32_t addr) {
    asm volatile("ldmatrix.sync.aligned.m8n8.x4.shared.b16 {%0,%1,%2,%3}, [%4];"
                 : "=r"(r[0]), "=r"(r[1]), "=r"(r[2]), "=r"(r[3]) : "r"(addr));
}
__device__ __forceinline__ float gelu_tanh(float x) {
    float u = 0.7978845608028654f * (x + 0.044715f * x * x * x);
    float e = __expf(2.0f * u);
    float t = 1.0f - __fdividef(2.0f, 1.0f + e);
    return 0.5f * x * (1.0f + t);
}

// ---------------------------------------------------------------------------
// Fused projection + weight-prep kernel.
// Blocks [0,128): proj — 8 local rows/block, W staged in smem, both sides.
// Blocks [128,143): split-bf16 weight packing into g_wpack.
// ---------------------------------------------------------------------------
#define PROJ_BLOCKS 128
#define PROJ_SMEM_BYTES ((DD * HH * 2 + 8 * DD) * 4)   // 64KB W + 8KB local

__global__ __launch_bounds__(256)
void proj_prep_kernel(const float* __restrict__ local,
                      const float* __restrict__ Wl,
                      const float* __restrict__ Wr,
                      const float* __restrict__ Wh,
                      const float* __restrict__ Wo) {
    const int bid = blockIdx.x;
    const int t   = threadIdx.x;

    if (bid >= PROJ_BLOCKS) {
        // ---- weight prep ----
        int gt = (bid - PROJ_BLOCKS) * 256 + t;      // 0..3839
        __nv_bfloat16* dst = (__nv_bfloat16*)g_wpack;
        if (gt < 32 * PITCHB) {
            int n = gt / PITCHB, k = gt % PITCHB;
            float w = (k < HH) ? Wh[k * HH + n] : 0.f;
            __nv_bfloat16 h = __float2bfloat16_rn(w);
            dst[gt]        = h;
            dst[1280 + gt] = __float2bfloat16_rn(w - __bfloat162float(h));
        } else if (gt < 32 * PITCHB + 64 * PITCHB) {
            int u = gt - 32 * PITCHB;
            int n = u / PITCHB, k = u % PITCHB;
            float w = (k < HH) ? Wo[k * OUTS + n] : 0.f;
            __nv_bfloat16 h = __float2bfloat16_rn(w);
            dst[2560 + u] = h;
            dst[5120 + u] = __float2bfloat16_rn(w - __bfloat162float(h));
        }
        return;
    }

    // ---- projection ----
    extern __shared__ float ps[];
    float* sWl  = ps;                    // 8192 floats
    float* sWr  = ps + DD * HH;          // 8192
    float* sLoc = ps + 2 * DD * HH;      // 8*256 = 2048

    // stage weights (float4, coalesced)
    {
        const float4* wl4 = reinterpret_cast<const float4*>(Wl);
        const float4* wr4 = reinterpret_cast<const float4*>(Wr);
        float4* dl = reinterpret_cast<float4*>(sWl);
        float4* dr = reinterpret_cast<float4*>(sWr);
#pragma unroll
        for (int q = 0; q < 8; ++q) {
            dl[t + 256 * q] = wl4[t + 256 * q];
            dr[t + 256 * q] = wr4[t + 256 * q];
        }
        const float4* lo4 = reinterpret_cast<const float4*>(local + (size_t)bid * 8 * DD);
        float4* dloc = reinterpret_cast<float4*>(sLoc);
#pragma unroll
        for (int q = 0; q < 2; ++q)
            dloc[t + 256 * q] = lo4[t + 256 * q];
    }
    __syncthreads();

    const int r = t >> 5, h = t & 31;    // warp = row, lane = h (coalesced out)
    const int n = bid * 8 + r;
    const float* lrow = sLoc + r * DD;

    float accL = 0.f, accR = 0.f;
#pragma unroll 16
    for (int d = 0; d < DD; ++d) {
        float v = lrow[d];               // broadcast within warp
        accL += v * sWl[d * HH + h];
        accR += v * sWr[d * HH + h];
    }
    g_left[n * HH + h]  = accL;
    g_right[n * HH + h] = accR;
}

// ---------------------------------------------------------------------------
// shared layout (byte offsets, all 16B aligned)
// ---------------------------------------------------------------------------
#define OFF_REL  0          // 65*36*4 = 9360
#define OFF_SL   9360       // 2048
#define OFF_SR   11408      // 2048
#define OFF_SC   13456      // 128
#define OFF_OF   13584      // 128
#define OFF_PM   13712      // 1024
#define OFF_PHI  14736      // 20480
#define OFF_PLO  35216      // 20480
#define OFF_WHH  55696      // 2560
#define OFF_WHL  58256      // 2560
#define OFF_WOH  60816      // 5120
#define OFF_WOL  65936      // 5120
#define SMEM_BYTES 71056

// ---------------------------------------------------------------------------
// Fused pair kernel: 16x16-pair tiles, 8 warps, split-bf16 mma + ldmatrix
// ---------------------------------------------------------------------------
__global__ __launch_bounds__(256, 2)
void pair_kernel(const int* __restrict__ resi,
                 const int* __restrict__ chain,
                 const int* __restrict__ batch,
                 const int* __restrict__ mask,
                 const float* __restrict__ W_relpos,
                 const float* __restrict__ ln_scale,
                 const float* __restrict__ ln_offset,
                 float* __restrict__ out) {
    extern __shared__ __align__(16) unsigned char smraw[];
    float*     sRel = (float*)(smraw + OFF_REL);
    float*     sL   = (float*)(smraw + OFF_SL);
    float*     sR   = (float*)(smraw + OFF_SR);
    float*     sSc  = (float*)(smraw + OFF_SC);
    float*     sOf  = (float*)(smraw + OFF_OF);
    int*       sPM  = (int*)(smraw + OFF_PM);
    uint32_t*  PHI  = (uint32_t*)(smraw + OFF_PHI);
    uint32_t*  PLO  = (uint32_t*)(smraw + OFF_PLO);

    const int t    = threadIdx.x;
    const int warp = t >> 5, lane = t & 31;
    const int g    = lane >> 2, tig = lane & 3;
    const int i0   = blockIdx.y * 16, j0 = blockIdx.x * 16;
    const int i    = i0 + (t >> 4), j = j0 + (t & 15);
    const int rbase = warp * 32;

    // ---- per-pair mask; block-level early exit ----
    const bool pm = (batch[i] == batch[j]) && (mask[i] != 0) && (mask[j] != 0);
    sPM[t] = pm;
    const int any = __syncthreads_or((int)pm);

    const float2 z2 = make_float2(0.f, 0.f);
    if (!any) {
#pragma unroll
        for (int mt = 0; mt < 2; ++mt) {
            const int r0 = rbase + mt * 16 + g, r1 = r0 + 8;
            float* p0 = out + ((size_t)((i0 + (r0 >> 4)) * NN + j0 + (r0 & 15))) * OUTS + 2 * tig;
            float* p1 = out + ((size_t)((i0 + (r1 >> 4)) * NN + j0 + (r1 & 15))) * OUTS + 2 * tig;
#pragma unroll
            for (int q = 0; q < 8; ++q) {
                __stcs(reinterpret_cast<float2*>(p0 + 8 * q), z2);
                __stcs(reinterpret_cast<float2*>(p1 + 8 * q), z2);
            }
        }
        return;
    }

    // ---- staging: rel table, L/R tiles, LN params, prepacked weights ----
    for (int idx = t; idx < NBINS * HH; idx += 256)
        sRel[(idx >> 5) * 36 + (idx & 31)] = W_relpos[idx];
    for (int idx = t; idx < 16 * HH; idx += 256) {
        sL[idx] = g_left[i0 * HH + idx];
        sR[idx] = g_right[j0 * HH + idx];
    }
    if (t < HH) { sSc[t] = ln_scale[t]; sOf[t] = ln_offset[t]; }
    {
        const uint4* src = (const uint4*)g_wpack;
        uint4* dst = (uint4*)(smraw + OFF_WHH);
#pragma unroll
        for (int idx = t; idx < 960; idx += 256) dst[idx] = src[idx];
    }
    __syncthreads();

    // ---- Phase A: pair build + layernorm -> split-bf16 rows ----
    {
        const bool same_chain = (batch[i] == batch[j]) && (chain[i] == chain[j]);
        int diff = resi[i] - resi[j];
        diff = min(max(diff, -32), 32) + 32;

        const float4* lp = reinterpret_cast<const float4*>(sL + (t >> 4) * HH);
        const float4* rp = reinterpret_cast<const float4*>(sR + (t & 15) * HH);
        const float4* ep = reinterpret_cast<const float4*>(&sRel[diff * 36]);

        float p[HH];
        float mu = 0.f;
#pragma unroll
        for (int h4 = 0; h4 < 8; ++h4) {
            float4 l = lp[h4], r = rp[h4], e = ep[h4];
            float4 v;
            v.x = l.x + r.x; v.y = l.y + r.y; v.z = l.z + r.z; v.w = l.w + r.w;
            if (same_chain) { v.x += e.x; v.y += e.y; v.z += e.z; v.w += e.w; }
            p[h4 * 4 + 0] = v.x; p[h4 * 4 + 1] = v.y;
            p[h4 * 4 + 2] = v.z; p[h4 * 4 + 3] = v.w;
            mu += v.x + v.y + v.z + v.w;
        }
        mu *= (1.f / HH);
        float var = 0.f;
#pragma unroll
        for (int h = 0; h < HH; ++h) { float d = p[h] - mu; var += d * d; }
        var *= (1.f / HH);
        const float rstd = rsqrtf(var + 1e-5f);

        uint32_t hiw[16], low[16];
#pragma unroll
        for (int k2 = 0; k2 < 16; ++k2) {
            float x0 = (p[2 * k2]     - mu) * rstd * sSc[2 * k2]     + sOf[2 * k2];
            float x1 = (p[2 * k2 + 1] - mu) * rstd * sSc[2 * k2 + 1] + sOf[2 * k2 + 1];
            split_pack(x0, x1, hiw[k2], low[k2]);
        }
        uint4* ph = reinterpret_cast<uint4*>(&PHI[t * PW]);
        uint4* pl = reinterpret_cast<uint4*>(&PLO[t * PW]);
#pragma unroll
        for (int q = 0; q < 4; ++q) {
            ph[q] = make_uint4(hiw[4 * q], hiw[4 * q + 1], hiw[4 * q + 2], hiw[4 * q + 3]);
            pl[q] = make_uint4(low[4 * q], low[4 * q + 1], low[4 * q + 2], low[4 * q + 3]);
        }
    }
    __syncthreads();

    // ---- ldmatrix base addresses (32-bit shared space) ----
    const uint32_t sbase = (uint32_t)__cvta_generic_to_shared(smraw);
    const uint32_t aBase = sbase + OFF_PHI +
        (uint32_t)(((rbase + (lane & 15)) * PW + (lane >> 4) * 4) << 2);
    const uint32_t bRow = (uint32_t)((8 * (lane >> 4) + (lane & 7)) * 80 +
                                     ((lane >> 3) & 1) * 16);
    const uint32_t b1Base = sbase + OFF_WHH + bRow;
    const uint32_t b2Base = sbase + OFF_WOH + bRow;

    // ---- GEMM1: C[256x32] = P @ Wh  (3-split mma), GELU in registers ----
    float acc1[2][4][4];
#pragma unroll
    for (int mt = 0; mt < 2; ++mt)
#pragma unroll
        for (int nt = 0; nt < 4; ++nt)
#pragma unroll
            for (int e = 0; e < 4; ++e) acc1[mt][nt][e] = 0.f;

#pragma unroll
    for (int kc = 0; kc < 2; ++kc) {
        uint32_t aH[2][4], aL[2][4];
        ldsm_x4(aH[0], aBase + kc * 32);
        ldsm_x4(aH[1], aBase + 1280 + kc * 32);
        ldsm_x4(aL[0], aBase + 20480 + kc * 32);
        ldsm_x4(aL[1], aBase + 20480 + 1280 + kc * 32);
        uint32_t bH[2][4], bL[2][4];
        ldsm_x4(bH[0], b1Base + kc * 32);            // nt 0,1 hi
        ldsm_x4(bH[1], b1Base + 1280 + kc * 32);     // nt 2,3 hi
        ldsm_x4(bL[0], b1Base + 2560 + kc * 32);     // nt 0,1 lo
        ldsm_x4(bL[1], b1Base + 3840 + kc * 32);     // nt 2,3 lo
#pragma unroll
        for (int nt = 0; nt < 4; ++nt) {
            const uint32_t bh0 = bH[nt >> 1][(nt & 1) * 2];
            const uint32_t bh1 = bH[nt >> 1][(nt & 1) * 2 + 1];
            const uint32_t bl0 = bL[nt >> 1][(nt & 1) * 2];
            const uint32_t bl1 = bL[nt >> 1][(nt & 1) * 2 + 1];
#pragma unroll
            for (int mt = 0; mt < 2; ++mt) {
                mma16816(acc1[mt][nt], aH[mt], bh0, bh1);
                mma16816(acc1[mt][nt], aH[mt], bl0, bl1);
                mma16816(acc1[mt][nt], aL[mt], bh0, bh1);
            }
        }
    }

    // GELU + re-split: C fragments become GEMM2 A fragments directly
    uint32_t hidH[2][2][4], hidL[2][2][4];   // [mt][kc][areg]
#pragma unroll
    for (int mt = 0; mt < 2; ++mt)
#pragma unroll
        for (int nt = 0; nt < 4; ++nt)
#pragma unroll
            for (int e = 0; e < 4; ++e)
                acc1[mt][nt][e] = gelu_tanh(acc1[mt][nt][e]);
#pragma unroll
    for (int mt = 0; mt < 2; ++mt)
#pragma unroll
        for (int kc = 0; kc < 2; ++kc) {
            const int n0 = 2 * kc, n1 = 2 * kc + 1;
            split_pack(acc1[mt][n0][0], acc1[mt][n0][1], hidH[mt][kc][0], hidL[mt][kc][0]);
            split_pack(acc1[mt][n0][2], acc1[mt][n0][3], hidH[mt][kc][1], hidL[mt][kc][1]);
            split_pack(acc1[mt][n1][0], acc1[mt][n1][1], hidH[mt][kc][2], hidL[mt][kc][2]);
            split_pack(acc1[mt][n1][2], acc1[mt][n1][3], hidH[mt][kc][3], hidL[mt][kc][3]);
        }

    // ---- GEMM2: out[256x64] = hid @ Wo, two n-halves of 32 cols ----
#pragma unroll
    for (int half = 0; half < 2; ++half) {
        float acc2[2][4][4];
#pragma unroll
        for (int mt = 0; mt < 2; ++mt)
#pragma unroll
            for (int q = 0; q < 4; ++q)
#pragma unroll
                for (int e = 0; e < 4; ++e) acc2[mt][q][e] = 0.f;

#pragma unroll
        for (int kc = 0; kc < 2; ++kc) {
#pragma unroll
            for (int p = 0; p < 2; ++p) {    // nt2 pair {half*4+2p, +1}
                uint32_t bh[4], bl[4];
                ldsm_x4(bh, b2Base + (half * 2 + p) * 1280 + kc * 32);
                ldsm_x4(bl, b2Base + 5120 + (half * 2 + p) * 1280 + kc * 32);
#pragma unroll
                for (int mt = 0; mt < 2; ++mt) {
                    mma16816(acc2[mt][2 * p],     hidH[mt][kc], bh[0], bh[1]);
                    mma16816(acc2[mt][2 * p],     hidH[mt][kc], bl[0], bl[1]);
                    mma16816(acc2[mt][2 * p],     hidL[mt][kc], bh[0], bh[1]);
                    mma16816(acc2[mt][2 * p + 1], hidH[mt][kc], bh[2], bh[3]);
                    mma16816(acc2[mt][2 * p + 1], hidH[mt][kc], bl[2], bl[3]);
                    mma16816(acc2[mt][2 * p + 1], hidL[mt][kc], bh[2], bh[3]);
                }
            }
        }

        // stores: row r, cols half*32 + 8q + 2tig (+1) — 8B sector-aligned
#pragma unroll
        for (int mt = 0; mt < 2; ++mt) {
            const int r0 = rbase + mt * 16 + g, r1 = r0 + 8;
            const bool m0 = sPM[r0], m1 = sPM[r1];
            float* p0 = out + ((size_t)((i0 + (r0 >> 4)) * NN + j0 + (r0 & 15))) * OUTS
                            + half * 32 + 2 * tig;
            float* p1 = out + ((size_t)((i0 + (r1 >> 4)) * NN + j0 + (r1 & 15))) * OUTS
                            + half * 32 + 2 * tig;
#pragma unroll
            for (int q = 0; q < 4; ++q) {
                float2 v0 = m0 ? make_float2(acc2[mt][q][0], acc2[mt][q][1]) : z2;
                float2 v1 = m1 ? make_float2(acc2[mt][q][2], acc2[mt][q][3]) : z2;
                __stcs(reinterpret_cast<float2*>(p0 + 8 * q), v0);
                __stcs(reinterpret_cast<float2*>(p1 + 8 * q), v1);
            }
        }
    }
}

// ---------------------------------------------------------------------------
extern "C" void kernel_launch(void* const* d_in, const int* in_sizes, int n_in,
                              void* d_out, int out_size) {
    const float* local = (const float*)d_in[0];
    const int*   resi  = (const int*)d_in[1];
    const int*   chain = (const int*)d_in[2];
    const int*   batch = (const int*)d_in[3];
    const int*   mask  = (const int*)d_in[4];
    const float* Wl    = (const float*)d_in[5];
    const float* Wr    = (const float*)d_in[6];
    const float* Wrel  = (const float*)d_in[7];
    const float* lns   = (const float*)d_in[8];
    const float* lno   = (const float*)d_in[9];
    const float* Wh    = (const float*)d_in[10];
    const float* Wo    = (const float*)d_in[11];
    float*       out   = (float*)d_out;

    static bool attr_set = false;
    if (!attr_set) {
        cudaFuncSetAttribute(pair_kernel,
                             cudaFuncAttributeMaxDynamicSharedMemorySize,
                             SMEM_BYTES);
        cudaFuncSetAttribute(proj_prep_kernel,
                             cudaFuncAttributeMaxDynamicSharedMemorySize,
                             PROJ_SMEM_BYTES);
        attr_set = true;
    }

    proj_prep_kernel<<<PROJ_BLOCKS + 15, 256, PROJ_SMEM_BYTES>>>(
        local, Wl, Wr, Wh, Wo);

    dim3 grid(NN / 16, NN / 16);
    pair_kernel<<<grid, 256, SMEM_BYTES>>>(resi, chain, batch, mask, Wrel,
                                           lns, lno, out);
}